// round 11
// baseline (speedup 1.0000x reference)
#include <cuda_runtime.h>
#include <cuda_bf16.h>

// ---------------- scratch (static device memory; no allocation) ----------------
__device__ float         g_P [65536ull * 512];   // q|k|v|g projections (row-major)
__device__ float         g_GA[65536ull * 128];   // gate * attn_out (row-major)
__device__ __nv_bfloat16 g_znh[8388608];          // layernormed z hi [token][128]
__device__ __nv_bfloat16 g_znl[8388608];          // layernormed z lo
__device__ __nv_bfloat16 g_Wh[65536], g_Wl[65536];   // packed q|k|v|g weights [512][128]
__device__ __nv_bfloat16 g_Oh[16384], g_Ol[16384];   // o_w [128][128]
__device__ float         g_Bcat[512];                 // packed q|k|v|g biases

typedef unsigned long long u64;

// ---------------- f32x2 packed-FMA helpers ----------------
__device__ __forceinline__ u64 frep2(float x) {
    u64 r; asm("mov.b64 %0, {%1, %1};" : "=l"(r) : "f"(x)); return r;
}
__device__ __forceinline__ u64 fpack2(float a, float b) {
    u64 r; asm("mov.b64 %0, {%1, %2};" : "=l"(r) : "f"(a), "f"(b)); return r;
}
__device__ __forceinline__ void ffma2(u64& d, u64 a, u64 b) {
    asm("fma.rn.f32x2 %0, %1, %2, %0;" : "+l"(d) : "l"(a), "l"(b));
}
__device__ __forceinline__ float2 funpk(u64 d) {
    float2 f; asm("mov.b64 {%0, %1}, %2;" : "=f"(f.x), "=f"(f.y) : "l"(d)); return f;
}

// ---------------- cp.async helpers ----------------
__device__ __forceinline__ void cpasync16(unsigned dst, const void* src) {
    asm volatile("cp.async.cg.shared.global [%0], [%1], 16;" :: "r"(dst), "l"(src));
}
#define CP_COMMIT() asm volatile("cp.async.commit_group;" ::: "memory")
#define CP_WAIT(n)  asm volatile("cp.async.wait_group %0;" :: "n"(n) : "memory")

// ---------------- tensor-core helpers ----------------
__device__ __forceinline__ unsigned smem_u32p(const void* p) {
    return (unsigned)__cvta_generic_to_shared(p);
}
__device__ __forceinline__ void ldmx4(unsigned* r, unsigned addr) {
    asm volatile("ldmatrix.sync.aligned.m8n8.x4.shared.b16 {%0,%1,%2,%3}, [%4];"
        : "=r"(r[0]), "=r"(r[1]), "=r"(r[2]), "=r"(r[3]) : "r"(addr));
}
__device__ __forceinline__ void ldmx2(unsigned* r, unsigned addr) {
    asm volatile("ldmatrix.sync.aligned.m8n8.x2.shared.b16 {%0,%1}, [%2];"
        : "=r"(r[0]), "=r"(r[1]) : "r"(addr));
}
__device__ __forceinline__ void mma16816(float* c, const unsigned* a, const unsigned* b) {
    asm volatile("mma.sync.aligned.m16n8k16.row.col.f32.bf16.bf16.f32 "
        "{%0,%1,%2,%3}, {%4,%5,%6,%7}, {%8,%9}, {%0,%1,%2,%3};"
        : "+f"(c[0]), "+f"(c[1]), "+f"(c[2]), "+f"(c[3])
        : "r"(a[0]), "r"(a[1]), "r"(a[2]), "r"(a[3]), "r"(b[0]), "r"(b[1]));
}
__device__ __forceinline__ void bf16split(float x, __nv_bfloat16& h, __nv_bfloat16& l) {
    h = __float2bfloat16_rn(x);
    l = __float2bfloat16_rn(x - __bfloat162float(h));
}

// ---------------- K0: pack + split weights ----------------
__global__ void pack_kernel(const float* __restrict__ qw, const float* __restrict__ kw,
                            const float* __restrict__ vw, const float* __restrict__ gw,
                            const float* __restrict__ qb, const float* __restrict__ kb,
                            const float* __restrict__ vb, const float* __restrict__ gb,
                            const float* __restrict__ ow) {
    int idx = blockIdx.x * 256 + threadIdx.x;   // 0 .. 81919
    if (idx < 65536) {
        int row = idx >> 7, col = idx & 127;
        const float* w = (row < 128) ? qw : (row < 256) ? kw : (row < 384) ? vw : gw;
        float x = w[(row & 127) * 128 + col];
        __nv_bfloat16 h, l; bf16split(x, h, l);
        g_Wh[idx] = h; g_Wl[idx] = l;
        if (idx < 512) {
            const float* b = (idx < 128) ? qb : (idx < 256) ? kb : (idx < 384) ? vb : gb;
            g_Bcat[idx] = b[idx & 127];
        }
    } else if (idx < 81920) {
        int i = idx - 65536;
        __nv_bfloat16 h, l; bf16split(ow[i], h, l);
        g_Oh[i] = h; g_Ol[i] = l;
    }
}

// ---------------- K1: LayerNorm -> bf16 hi/lo ----------------
__global__ void ln_kernel(const float* __restrict__ z,
                          const float* __restrict__ lw,
                          const float* __restrict__ lb) {
    int warp = threadIdx.x >> 5, lane = threadIdx.x & 31;
    int t = blockIdx.x * 8 + warp;
    const float4* zp = (const float4*)(z + (size_t)t * 128);
    float4 v = zp[lane];
    float s = v.x + v.y + v.z + v.w;
    float q = v.x * v.x + v.y * v.y + v.z * v.z + v.w * v.w;
    #pragma unroll
    for (int o = 16; o; o >>= 1) {
        s += __shfl_xor_sync(0xFFFFFFFFu, s, o);
        q += __shfl_xor_sync(0xFFFFFFFFu, q, o);
    }
    float mu  = s * (1.0f / 128.0f);
    float var = q * (1.0f / 128.0f) - mu * mu;
    float rs  = rsqrtf(var + 1e-5f);
    float4 w4 = ((const float4*)lw)[lane];
    float4 b4 = ((const float4*)lb)[lane];
    float o4[4];
    o4[0] = (v.x - mu) * rs * w4.x + b4.x;
    o4[1] = (v.y - mu) * rs * w4.y + b4.y;
    o4[2] = (v.z - mu) * rs * w4.z + b4.z;
    o4[3] = (v.w - mu) * rs * w4.w + b4.w;
    __nv_bfloat16 h[4], l[4];
    #pragma unroll
    for (int i = 0; i < 4; i++) bf16split(o4[i], h[i], l[i]);
    size_t base = (size_t)t * 128 + lane * 4;
    *(__nv_bfloat162*)(g_znh + base)     = __nv_bfloat162(h[0], h[1]);
    *(__nv_bfloat162*)(g_znh + base + 2) = __nv_bfloat162(h[2], h[3]);
    *(__nv_bfloat162*)(g_znl + base)     = __nv_bfloat162(l[0], l[1]);
    *(__nv_bfloat162*)(g_znl + base + 2) = __nv_bfloat162(l[2], l[3]);
}

// ---------------- K2/K4: bf16-split tensor-core GEMM (unchanged) ----------------
template<int MODE>
__global__ void __launch_bounds__(256, 2) mma_gemm(const float* __restrict__ obias,
                                                   const int*   __restrict__ mask,
                                                   float* __restrict__ Cout) {
    extern __shared__ __nv_bfloat16 smem[];
    __nv_bfloat16* sAh = smem;             // 64*136
    __nv_bfloat16* sAl = smem + 8704;
    __nv_bfloat16* sBh = smem + 17408;     // 128*136
    __nv_bfloat16* sBl = smem + 34816;
    int tid = threadIdx.x;
    int bm0 = blockIdx.x * 64;
    int bn0 = (MODE == 1) ? blockIdx.y * 128 : 0;

    if (MODE == 1) {
        const uint4* srcH = (const uint4*)(g_znh + (size_t)bm0 * 128);
        const uint4* srcL = (const uint4*)(g_znl + (size_t)bm0 * 128);
        uint4* dAh = (uint4*)sAh; uint4* dAl = (uint4*)sAl;
        #pragma unroll
        for (int it = 0; it < 4; it++) {
            int idx = it * 256 + tid;
            int row = idx >> 4, ch = idx & 15;
            dAh[row * 17 + ch] = srcH[idx];
            dAl[row * 17 + ch] = srcL[idx];
        }
    } else {
        const float4* srcA = (const float4*)(g_GA + (size_t)bm0 * 128);
        #pragma unroll
        for (int it = 0; it < 8; it++) {
            int idx = it * 256 + tid;
            int row = idx >> 5, c4 = idx & 31;
            float4 v = srcA[idx];
            int col = c4 * 4;
            __nv_bfloat16 h, l;
            bf16split(v.x, h, l); sAh[row * 136 + col]     = h; sAl[row * 136 + col]     = l;
            bf16split(v.y, h, l); sAh[row * 136 + col + 1] = h; sAl[row * 136 + col + 1] = l;
            bf16split(v.z, h, l); sAh[row * 136 + col + 2] = h; sAl[row * 136 + col + 2] = l;
            bf16split(v.w, h, l); sAh[row * 136 + col + 3] = h; sAl[row * 136 + col + 3] = l;
        }
    }
    {
        const __nv_bfloat16* BH = (MODE == 1) ? g_Wh : g_Oh;
        const __nv_bfloat16* BL = (MODE == 1) ? g_Wl : g_Ol;
        const uint4* srcH = (const uint4*)(BH + (size_t)bn0 * 128);
        const uint4* srcL = (const uint4*)(BL + (size_t)bn0 * 128);
        uint4* dBh = (uint4*)sBh; uint4* dBl = (uint4*)sBl;
        #pragma unroll
        for (int it = 0; it < 8; it++) {
            int idx = it * 256 + tid;
            int row = idx >> 4, ch = idx & 15;
            dBh[row * 17 + ch] = srcH[idx];
            dBl[row * 17 + ch] = srcL[idx];
        }
    }
    __syncthreads();

    int wid = tid >> 5, lane = tid & 31;
    int warp_m = (wid & 1) * 32, warp_n = (wid >> 1) * 32;
    unsigned baseAh = smem_u32p(sAh), baseAl = smem_u32p(sAl);
    unsigned baseBh = smem_u32p(sBh), baseBl = smem_u32p(sBl);
    int arow = warp_m + (lane & 15);
    int kofa = (lane >> 4) * 8;
    int brow = warp_n + (lane & 7);
    int kofb = ((lane >> 3) & 1) * 8;

    float acc[2][4][4];
    #pragma unroll
    for (int mi = 0; mi < 2; mi++)
        #pragma unroll
        for (int ni = 0; ni < 4; ni++)
            #pragma unroll
            for (int c = 0; c < 4; c++) acc[mi][ni][c] = 0.0f;

    #pragma unroll
    for (int ks = 0; ks < 8; ks++) {
        unsigned ah[2][4], al[2][4], bh[4][2], bl[4][2];
        #pragma unroll
        for (int mi = 0; mi < 2; mi++) {
            unsigned ao = (unsigned)((arow + mi * 16) * 272 + (ks * 16 + kofa) * 2);
            ldmx4(ah[mi], baseAh + ao);
            ldmx4(al[mi], baseAl + ao);
        }
        #pragma unroll
        for (int ni = 0; ni < 4; ni++) {
            unsigned bo = (unsigned)((brow + ni * 8) * 272 + (ks * 16 + kofb) * 2);
            ldmx2(bh[ni], baseBh + bo);
            ldmx2(bl[ni], baseBl + bo);
        }
        #pragma unroll
        for (int mi = 0; mi < 2; mi++)
            #pragma unroll
            for (int ni = 0; ni < 4; ni++) {
                mma16816(acc[mi][ni], ah[mi], bh[ni]);
                mma16816(acc[mi][ni], ah[mi], bl[ni]);
                mma16816(acc[mi][ni], al[mi], bh[ni]);
            }
    }

    #pragma unroll
    for (int mi = 0; mi < 2; mi++)
        #pragma unroll
        for (int ni = 0; ni < 4; ni++) {
            int row = bm0 + warp_m + mi * 16 + (lane >> 2);
            int col = bn0 + warp_n + ni * 8 + (lane & 3) * 2;
            if (MODE == 1) {
                float b0 = g_Bcat[col], b1 = g_Bcat[col + 1];
                *(float2*)&g_P[(size_t)row * 512 + col] =
                    make_float2(acc[mi][ni][0] + b0, acc[mi][ni][1] + b1);
                *(float2*)&g_P[(size_t)(row + 8) * 512 + col] =
                    make_float2(acc[mi][ni][2] + b0, acc[mi][ni][3] + b1);
            } else {
                float b0 = obias[col], b1 = obias[col + 1];
                float m0 = (float)mask[row], m1 = (float)mask[row + 8];
                *(float2*)&Cout[(size_t)row * 128 + col] =
                    make_float2((acc[mi][ni][0] + b0) * m0, (acc[mi][ni][1] + b1) * m0);
                *(float2*)&Cout[(size_t)(row + 8) * 128 + col] =
                    make_float2((acc[mi][ni][2] + b0) * m1, (acc[mi][ni][3] + b1) * m1);
            }
        }
}

// ---------------- K3: attn — cp.async pipelined, 2 CTAs/SM ----------------
// grid (256 rows, 4 heads), 256 threads, dyn smem 115840 B.
// floats: R1  @0     [9216]: kf[128][66] | kvp[2][4][1024]+ksp[256] | g/out [256][36]
//         R2a @9216  [4608]: k [128][36]; later kv[2048]+ks[64]
//         R2b @13824 [4608]: v [128][36]   (mask NOT applied to v: kf carries it, mask in {0,1})
//         s_q @18432 [9216]: q [256][36]
//         s_w @27648 [1056], s_mask @28704 [256]
__global__ void __launch_bounds__(256, 2) attn_kernel(const int*   __restrict__ pm,
                                                      const float* __restrict__ qfw,
                                                      const float* __restrict__ qfb,
                                                      const float* __restrict__ kfw,
                                                      const float* __restrict__ kfb) {
    extern __shared__ float sm[];
    float* R1     = sm;             // 9216
    float* R2a    = sm + 9216;      // 4608
    float* R2b    = sm + 13824;     // 4608
    float* s_q    = sm + 18432;     // 9216
    float* s_w    = sm + 27648;     // 1056
    float* s_mask = sm + 28704;     // 256

    unsigned R1u  = smem_u32p(R1);
    unsigned R2au = smem_u32p(R2a);
    unsigned R2bu = smem_u32p(R2b);
    unsigned squ  = smem_u32p(s_q);

    int tid = threadIdx.x;
    int r = blockIdx.x, h = blockIdx.y;
    int t0 = r * 256;
    int lane = tid & 31, w = tid >> 5;

    // ---- prologue: issue k chunk0 + full q via cp.async ----
    {
        const float* Pk0 = g_P + (size_t)t0 * 512 + 128 + h * 32;
        #pragma unroll
        for (int it = 0; it < 4; it++) {
            int idx = it * 256 + tid;
            int token = idx >> 3, c4 = idx & 7;
            cpasync16(R2au + (unsigned)(token * 36 + c4 * 4) * 4,
                      Pk0 + (size_t)token * 512 + c4 * 4);
        }
        CP_COMMIT();
        const float* Pq0 = g_P + (size_t)t0 * 512 + h * 32;
        #pragma unroll
        for (int it = 0; it < 8; it++) {
            int idx = it * 256 + tid;
            int token = idx >> 3, c4 = idx & 7;
            cpasync16(squ + (unsigned)(token * 36 + c4 * 4) * 4,
                      Pq0 + (size_t)token * 512 + c4 * 4);
        }
        CP_COMMIT();
    }

    for (int i = tid; i < 1024; i += 256) s_w[i] = kfw[i];
    if (tid < 32) s_w[1024 + tid] = kfb[tid];
    s_mask[tid] = (float)pm[t0 + tid];

    // step-B decomposition: warp = (fhalf, tgroup); lane = (fy, dx); 4f x 8d per lane
    int fhalf = w & 1, tg = w >> 1;
    int fy = lane >> 2, dx = lane & 3;
    int fbase = fhalf * 32 + fy * 4;
    u64 acc2[4][4];
    float ks[4];
    #pragma unroll
    for (int j = 0; j < 4; j++) {
        ks[j] = 0.0f;
        #pragma unroll
        for (int q = 0; q < 4; q++) acc2[j][q] = 0ull;
    }

    #pragma unroll 1
    for (int c = 0; c < 2; c++) {
        if (c == 0) { CP_WAIT(1); } else { CP_WAIT(0); }   // current k chunk ready
        __syncthreads();
        // issue v chunk c (pure copy — no mask; kf carries the 0/1 mask)
        {
            const float* Pv = g_P + (size_t)(t0 + c * 128) * 512 + 256 + h * 32;
            #pragma unroll
            for (int it = 0; it < 4; it++) {
                int idx = it * 256 + tid;
                int token = idx >> 3, c4 = idx & 7;
                cpasync16(R2bu + (unsigned)(token * 36 + c4 * 4) * 4,
                          Pv + (size_t)token * 512 + c4 * 4);
            }
            CP_COMMIT();
        }
        // ---- features: thread -> (token = tid&127, rows hh*16..+15) ----
        {
            int tk = tid & 127, hh = tid >> 7;
            float mk = s_mask[c * 128 + tk];
            const ulonglong2* kp = (const ulonglong2*)(R2a + tk * 36);
            u64 k2[16];
            #pragma unroll
            for (int i = 0; i < 8; i++) {
                ulonglong2 kk = kp[i];
                k2[2 * i] = kk.x; k2[2 * i + 1] = kk.y;
            }
            #pragma unroll
            for (int rr = 0; rr < 16; rr++) {
                int row = hh * 16 + rr;
                const u64* wr = (const u64*)&s_w[row * 32];   // broadcast LDS.64
                u64 a2 = 0ull, b2 = 0ull;
                #pragma unroll
                for (int dp = 0; dp < 8; dp++) {
                    ffma2(a2, wr[2 * dp],     k2[2 * dp]);
                    ffma2(b2, wr[2 * dp + 1], k2[2 * dp + 1]);
                }
                float2 fa = funpk(a2), fb = funpk(b2);
                float m = (fa.x + fa.y) + (fb.x + fb.y) + s_w[1024 + row];
                m = fminf(8.0f, fmaxf(-8.0f, m));
                R1[tk * 66 + row]      = __expf(m)  * mk;
                R1[tk * 66 + 32 + row] = __expf(-m) * mk;
            }
        }
        __syncthreads();   // features done reading R2a (k)
        if (c == 0) {
            // issue k chunk1 into R2a
            const float* Pk1 = g_P + (size_t)(t0 + 128) * 512 + 128 + h * 32;
            #pragma unroll
            for (int it = 0; it < 4; it++) {
                int idx = it * 256 + tid;
                int token = idx >> 3, c4 = idx & 7;
                cpasync16(R2au + (unsigned)(token * 36 + c4 * 4) * 4,
                          Pk1 + (size_t)token * 512 + c4 * 4);
            }
            CP_COMMIT();
            CP_WAIT(1);    // q + v0 done; k1 in flight
        } else {
            CP_WAIT(0);    // v1 done
        }
        __syncthreads();
        // ---- step B: 32 tokens per warp per chunk ----
        #pragma unroll 2
        for (int i = 0; i < 32; i++) {
            int nn = tg * 32 + i;
            float2 kfa  = *(const float2*)&R1[nn * 66 + fbase];
            float2 kfb2 = *(const float2*)&R1[nn * 66 + fbase + 2];
            u64 kf2[4];
            kf2[0] = frep2(kfa.x);  kf2[1] = frep2(kfa.y);
            kf2[2] = frep2(kfb2.x); kf2[3] = frep2(kfb2.y);
            const ulonglong2* vmp = (const ulonglong2*)(R2b + nn * 36 + dx * 8);
            ulonglong2 v0 = vmp[0], v1 = vmp[1];
            u64 vm2[4] = {v0.x, v0.y, v1.x, v1.y};
            #pragma unroll
            for (int j = 0; j < 4; j++)
                #pragma unroll
                for (int q = 0; q < 4; q++) ffma2(acc2[j][q], kf2[j], vm2[q]);
            if (dx == 0) {
                ks[0] += kfa.x; ks[1] += kfa.y; ks[2] += kfb2.x; ks[3] += kfb2.y;
            }
        }
        __syncthreads();   // step B done reading R1 (kf) / R2b (v)
    }

    // ---- spill partials into R1: kvp[2][4][1024] + ksp[256] ----
    float* kvp = R1;
    float* ksp = R1 + 8192;
    #pragma unroll
    for (int j = 0; j < 4; j++) {
        float2 u0 = funpk(acc2[j][0]), u1 = funpk(acc2[j][1]);
        float2 u2 = funpk(acc2[j][2]), u3 = funpk(acc2[j][3]);
        float* dst = &kvp[fhalf * 4096 + tg * 1024 + (fy * 4 + j) * 32 + dx * 8];
        *(float4*)dst       = make_float4(u0.x, u0.y, u1.x, u1.y);
        *(float4*)(dst + 4) = make_float4(u2.x, u2.y, u3.x, u3.y);
    }
    if (dx == 0) {
        #pragma unroll
        for (int j = 0; j < 4; j++) ksp[fhalf * 128 + tg * 32 + fy * 4 + j] = ks[j];
    }
    for (int i = tid; i < 1024; i += 256) s_w[i] = qfw[i];
    if (tid < 32) s_w[1024 + tid] = qfb[tid];
    __syncthreads();

    // ---- reduce 4 copies -> s_kv[2048] + s_ks[64] in R2a (k space free) ----
    float* s_kv = R2a;
    float* s_ks = R2a + 2048;
    {
        int e = tid * 8;
        int f = e >> 5, d0 = e & 31;
        const float* src = &kvp[(f >> 5) * 4096 + (f & 31) * 32 + d0];
        float4 r0 = make_float4(0, 0, 0, 0), r1 = make_float4(0, 0, 0, 0);
        #pragma unroll
        for (int c2 = 0; c2 < 4; c2++) {
            float4 p0 = *(const float4*)(src + c2 * 1024);
            float4 p1 = *(const float4*)(src + c2 * 1024 + 4);
            r0.x += p0.x; r0.y += p0.y; r0.z += p0.z; r0.w += p0.w;
            r1.x += p1.x; r1.y += p1.y; r1.z += p1.z; r1.w += p1.w;
        }
        *(float4*)&s_kv[e]     = r0;
        *(float4*)&s_kv[e + 4] = r1;
        if (tid < 64) {
            float s = 0.0f;
            #pragma unroll
            for (int c2 = 0; c2 < 4; c2++) s += ksp[(tid >> 5) * 128 + c2 * 32 + (tid & 31)];
            s_ks[tid] = s;
        }
    }
    __syncthreads();

    // ---- issue g via cp.async into R1 [256][36] (kvp consumed); step C hides it ----
    {
        const float* Pg0 = g_P + (size_t)t0 * 512 + 384 + h * 32;
        #pragma unroll
        for (int it = 0; it < 8; it++) {
            int idx = it * 256 + tid;
            int token = idx >> 3, c4 = idx & 7;
            cpasync16(R1u + (unsigned)(token * 36 + c4 * 4) * 4,
                      Pg0 + (size_t)token * 512 + c4 * 4);
        }
        CP_COMMIT();
    }

    // ---- step C: qf features (q from s_q), num/den ----
    u64 num2[16];
    #pragma unroll
    for (int q = 0; q < 16; q++) num2[q] = 0ull;
    float den = 0.0f;
    {
        const ulonglong2* qp = (const ulonglong2*)(s_q + tid * 36);
        u64 q2[16];
        #pragma unroll
        for (int i = 0; i < 8; i++) {
            ulonglong2 qq = qp[i];
            q2[2 * i] = qq.x; q2[2 * i + 1] = qq.y;
        }
        #pragma unroll 4
        for (int row = 0; row < 32; row++) {
            const u64* wr = (const u64*)&s_w[row * 32];   // broadcast LDS.64
            u64 a2 = 0ull, b2 = 0ull;
            #pragma unroll
            for (int dp = 0; dp < 8; dp++) {
                ffma2(a2, wr[2 * dp],     q2[2 * dp]);
                ffma2(b2, wr[2 * dp + 1], q2[2 * dp + 1]);
            }
            float2 fa = funpk(a2), fb = funpk(b2);
            float m = (fa.x + fa.y) + (fb.x + fb.y) + s_w[1024 + row];
            m = fminf(8.0f, fmaxf(-8.0f, m));
            float e  = __expf(m);
            float ei = __expf(-m);
            den += e  * s_ks[row];
            den += ei * s_ks[row + 32];
            u64 e2 = frep2(e), ei2 = frep2(ei);
            const ulonglong2* k1 = (const ulonglong2*)&s_kv[row * 32];
            const ulonglong2* k2 = (const ulonglong2*)&s_kv[(row + 32) * 32];
            #pragma unroll
            for (int q = 0; q < 8; q++) {
                ulonglong2 ka = k1[q];
                ffma2(num2[2 * q],     e2, ka.x);
                ffma2(num2[2 * q + 1], e2, ka.y);
            }
            #pragma unroll
            for (int q = 0; q < 8; q++) {
                ulonglong2 kb = k2[q];
                ffma2(num2[2 * q],     ei2, kb.x);
                ffma2(num2[2 * q + 1], ei2, kb.y);
            }
        }
    }
    den = fmaxf(den, 1e-6f);
    float inv = 1.0f / den;
    CP_WAIT(0);        // g landed
    __syncthreads();

    // ---- gate in place (R1 stride 36), coop store ----
    {
        float* grow = R1 + tid * 36;
        #pragma unroll
        for (int i = 0; i < 8; i++) {
            float2 ua = funpk(num2[2 * i]);
            float2 ub = funpk(num2[2 * i + 1]);
            float4 gv = *(float4*)(grow + 4 * i);
            float4 o;
            o.x = __fdividef(1.0f, 1.0f + __expf(-gv.x)) * ua.x * inv;
            o.y = __fdividef(1.0f, 1.0f + __expf(-gv.y)) * ua.y * inv;
            o.z = __fdividef(1.0f, 1.0f + __expf(-gv.z)) * ub.x * inv;
            o.w = __fdividef(1.0f, 1.0f + __expf(-gv.w)) * ub.y * inv;
            *(float4*)(grow + 4 * i) = o;
        }
    }
    __syncthreads();
    {
        float* GA0 = g_GA + (size_t)t0 * 128 + h * 32;
        #pragma unroll
        for (int it = 0; it < 8; it++) {
            int idx = it * 256 + tid;
            int token = idx >> 3, c4 = idx & 7;
            float4 o = *(const float4*)(R1 + token * 36 + c4 * 4);
            *(float4*)(GA0 + (size_t)token * 128 + c4 * 4) = o;
        }
    }
}

// ---------------- launcher ----------------
extern "C" void kernel_launch(void* const* d_in, const int* in_sizes, int n_in,
                              void* d_out, int out_size) {
    const float* z    = (const float*)d_in[0];
    const int*   pm   = (const int*)  d_in[1];
    const float* lnw  = (const float*)d_in[2];
    const float* lnb  = (const float*)d_in[3];
    const float* qw   = (const float*)d_in[4];
    const float* qb   = (const float*)d_in[5];
    const float* kw   = (const float*)d_in[6];
    const float* kb   = (const float*)d_in[7];
    const float* vw   = (const float*)d_in[8];
    const float* vb   = (const float*)d_in[9];
    const float* qfw  = (const float*)d_in[10];
    const float* qfb  = (const float*)d_in[11];
    const float* kfw  = (const float*)d_in[12];
    const float* kfb  = (const float*)d_in[13];
    const float* gw   = (const float*)d_in[14];
    const float* gb   = (const float*)d_in[15];
    const float* ow   = (const float*)d_in[16];
    const float* ob   = (const float*)d_in[17];
    float* out = (float*)d_out;

    static int attr_set = 0;
    if (!attr_set) {
        cudaFuncSetAttribute(attn_kernel, cudaFuncAttributeMaxDynamicSharedMemorySize, 115840);
        cudaFuncSetAttribute(mma_gemm<1>, cudaFuncAttributeMaxDynamicSharedMemorySize, 104448);
        cudaFuncSetAttribute(mma_gemm<2>, cudaFuncAttributeMaxDynamicSharedMemorySize, 104448);
        attr_set = 1;
    }

    pack_kernel<<<320, 256>>>(qw, kw, vw, gw, qb, kb, vb, gb, ow);
    ln_kernel<<<8192, 256>>>(z, lnw, lnb);
    mma_gemm<1><<<dim3(1024, 4), 256, 104448>>>(nullptr, nullptr, nullptr);
    attn_kernel<<<dim3(256, 4), 256, 115840>>>(pm, qfw, qfb, kfw, kfb);
    mma_gemm<2><<<dim3(1024, 1), 256, 104448>>>(ob, pm, out);
}

// round 12
// speedup vs baseline: 1.0913x; 1.0913x over previous
#include <cuda_runtime.h>
#include <cuda_bf16.h>

// ---------------- scratch (static device memory; no allocation) ----------------
__device__ float         g_P [65536ull * 512];   // q|k|v|g projections (row-major)
__device__ float         g_GA[65536ull * 128];   // gate * attn_out (row-major)
__device__ __nv_bfloat16 g_znh[8388608];          // layernormed z hi [token][128]
__device__ __nv_bfloat16 g_znl[8388608];          // layernormed z lo
__device__ __nv_bfloat16 g_Wh[65536], g_Wl[65536];   // packed q|k|v|g weights [512][128]
__device__ __nv_bfloat16 g_Oh[16384], g_Ol[16384];   // o_w [128][128]
__device__ float         g_Bcat[512];                 // packed q|k|v|g biases

typedef unsigned long long u64;

// ---------------- f32x2 packed-FMA helpers ----------------
__device__ __forceinline__ u64 frep2(float x) {
    u64 r; asm("mov.b64 %0, {%1, %1};" : "=l"(r) : "f"(x)); return r;
}
__device__ __forceinline__ u64 fpack2(float a, float b) {
    u64 r; asm("mov.b64 %0, {%1, %2};" : "=l"(r) : "f"(a), "f"(b)); return r;
}
__device__ __forceinline__ void ffma2(u64& d, u64 a, u64 b) {
    asm("fma.rn.f32x2 %0, %1, %2, %0;" : "+l"(d) : "l"(a), "l"(b));
}
__device__ __forceinline__ float2 funpk(u64 d) {
    float2 f; asm("mov.b64 {%0, %1}, %2;" : "=f"(f.x), "=f"(f.y) : "l"(d)); return f;
}

// ---------------- cp.async helpers ----------------
__device__ __forceinline__ void cpasync16(unsigned dst, const void* src) {
    asm volatile("cp.async.cg.shared.global [%0], [%1], 16;" :: "r"(dst), "l"(src));
}
#define CP_COMMIT() asm volatile("cp.async.commit_group;" ::: "memory")
#define CP_WAIT(n)  asm volatile("cp.async.wait_group %0;" :: "n"(n) : "memory")

// ---------------- tensor-core helpers ----------------
__device__ __forceinline__ unsigned smem_u32p(const void* p) {
    return (unsigned)__cvta_generic_to_shared(p);
}
__device__ __forceinline__ void ldmx4(unsigned* r, unsigned addr) {
    asm volatile("ldmatrix.sync.aligned.m8n8.x4.shared.b16 {%0,%1,%2,%3}, [%4];"
        : "=r"(r[0]), "=r"(r[1]), "=r"(r[2]), "=r"(r[3]) : "r"(addr));
}
__device__ __forceinline__ void ldmx2(unsigned* r, unsigned addr) {
    asm volatile("ldmatrix.sync.aligned.m8n8.x2.shared.b16 {%0,%1}, [%2];"
        : "=r"(r[0]), "=r"(r[1]) : "r"(addr));
}
__device__ __forceinline__ void mma16816(float* c, const unsigned* a, const unsigned* b) {
    asm volatile("mma.sync.aligned.m16n8k16.row.col.f32.bf16.bf16.f32 "
        "{%0,%1,%2,%3}, {%4,%5,%6,%7}, {%8,%9}, {%0,%1,%2,%3};"
        : "+f"(c[0]), "+f"(c[1]), "+f"(c[2]), "+f"(c[3])
        : "r"(a[0]), "r"(a[1]), "r"(a[2]), "r"(a[3]), "r"(b[0]), "r"(b[1]));
}
__device__ __forceinline__ void bf16split(float x, __nv_bfloat16& h, __nv_bfloat16& l) {
    h = __float2bfloat16_rn(x);
    l = __float2bfloat16_rn(x - __bfloat162float(h));
}

// ---------------- K0: pack + split weights ----------------
__global__ void pack_kernel(const float* __restrict__ qw, const float* __restrict__ kw,
                            const float* __restrict__ vw, const float* __restrict__ gw,
                            const float* __restrict__ qb, const float* __restrict__ kb,
                            const float* __restrict__ vb, const float* __restrict__ gb,
                            const float* __restrict__ ow) {
    int idx = blockIdx.x * 256 + threadIdx.x;   // 0 .. 81919
    if (idx < 65536) {
        int row = idx >> 7, col = idx & 127;
        const float* w = (row < 128) ? qw : (row < 256) ? kw : (row < 384) ? vw : gw;
        float x = w[(row & 127) * 128 + col];
        __nv_bfloat16 h, l; bf16split(x, h, l);
        g_Wh[idx] = h; g_Wl[idx] = l;
        if (idx < 512) {
            const float* b = (idx < 128) ? qb : (idx < 256) ? kb : (idx < 384) ? vb : gb;
            g_Bcat[idx] = b[idx & 127];
        }
    } else if (idx < 81920) {
        int i = idx - 65536;
        __nv_bfloat16 h, l; bf16split(ow[i], h, l);
        g_Oh[i] = h; g_Ol[i] = l;
    }
}

// ---------------- K1: LayerNorm -> bf16 hi/lo ----------------
__global__ void ln_kernel(const float* __restrict__ z,
                          const float* __restrict__ lw,
                          const float* __restrict__ lb) {
    int warp = threadIdx.x >> 5, lane = threadIdx.x & 31;
    int t = blockIdx.x * 8 + warp;
    const float4* zp = (const float4*)(z + (size_t)t * 128);
    float4 v = zp[lane];
    float s = v.x + v.y + v.z + v.w;
    float q = v.x * v.x + v.y * v.y + v.z * v.z + v.w * v.w;
    #pragma unroll
    for (int o = 16; o; o >>= 1) {
        s += __shfl_xor_sync(0xFFFFFFFFu, s, o);
        q += __shfl_xor_sync(0xFFFFFFFFu, q, o);
    }
    float mu  = s * (1.0f / 128.0f);
    float var = q * (1.0f / 128.0f) - mu * mu;
    float rs  = rsqrtf(var + 1e-5f);
    float4 w4 = ((const float4*)lw)[lane];
    float4 b4 = ((const float4*)lb)[lane];
    float o4[4];
    o4[0] = (v.x - mu) * rs * w4.x + b4.x;
    o4[1] = (v.y - mu) * rs * w4.y + b4.y;
    o4[2] = (v.z - mu) * rs * w4.z + b4.z;
    o4[3] = (v.w - mu) * rs * w4.w + b4.w;
    __nv_bfloat16 h[4], l[4];
    #pragma unroll
    for (int i = 0; i < 4; i++) bf16split(o4[i], h[i], l[i]);
    size_t base = (size_t)t * 128 + lane * 4;
    *(__nv_bfloat162*)(g_znh + base)     = __nv_bfloat162(h[0], h[1]);
    *(__nv_bfloat162*)(g_znh + base + 2) = __nv_bfloat162(h[2], h[3]);
    *(__nv_bfloat162*)(g_znl + base)     = __nv_bfloat162(l[0], l[1]);
    *(__nv_bfloat162*)(g_znl + base + 2) = __nv_bfloat162(l[2], l[3]);
}

// ---------------- K2/K4: bf16-split tensor-core GEMM (unchanged) ----------------
template<int MODE>
__global__ void __launch_bounds__(256, 2) mma_gemm(const float* __restrict__ obias,
                                                   const int*   __restrict__ mask,
                                                   float* __restrict__ Cout) {
    extern __shared__ __nv_bfloat16 smem[];
    __nv_bfloat16* sAh = smem;             // 64*136
    __nv_bfloat16* sAl = smem + 8704;
    __nv_bfloat16* sBh = smem + 17408;     // 128*136
    __nv_bfloat16* sBl = smem + 34816;
    int tid = threadIdx.x;
    int bm0 = blockIdx.x * 64;
    int bn0 = (MODE == 1) ? blockIdx.y * 128 : 0;

    if (MODE == 1) {
        const uint4* srcH = (const uint4*)(g_znh + (size_t)bm0 * 128);
        const uint4* srcL = (const uint4*)(g_znl + (size_t)bm0 * 128);
        uint4* dAh = (uint4*)sAh; uint4* dAl = (uint4*)sAl;
        #pragma unroll
        for (int it = 0; it < 4; it++) {
            int idx = it * 256 + tid;
            int row = idx >> 4, ch = idx & 15;
            dAh[row * 17 + ch] = srcH[idx];
            dAl[row * 17 + ch] = srcL[idx];
        }
    } else {
        const float4* srcA = (const float4*)(g_GA + (size_t)bm0 * 128);
        #pragma unroll
        for (int it = 0; it < 8; it++) {
            int idx = it * 256 + tid;
            int row = idx >> 5, c4 = idx & 31;
            float4 v = srcA[idx];
            int col = c4 * 4;
            __nv_bfloat16 h, l;
            bf16split(v.x, h, l); sAh[row * 136 + col]     = h; sAl[row * 136 + col]     = l;
            bf16split(v.y, h, l); sAh[row * 136 + col + 1] = h; sAl[row * 136 + col + 1] = l;
            bf16split(v.z, h, l); sAh[row * 136 + col + 2] = h; sAl[row * 136 + col + 2] = l;
            bf16split(v.w, h, l); sAh[row * 136 + col + 3] = h; sAl[row * 136 + col + 3] = l;
        }
    }
    {
        const __nv_bfloat16* BH = (MODE == 1) ? g_Wh : g_Oh;
        const __nv_bfloat16* BL = (MODE == 1) ? g_Wl : g_Ol;
        const uint4* srcH = (const uint4*)(BH + (size_t)bn0 * 128);
        const uint4* srcL = (const uint4*)(BL + (size_t)bn0 * 128);
        uint4* dBh = (uint4*)sBh; uint4* dBl = (uint4*)sBl;
        #pragma unroll
        for (int it = 0; it < 8; it++) {
            int idx = it * 256 + tid;
            int row = idx >> 4, ch = idx & 15;
            dBh[row * 17 + ch] = srcH[idx];
            dBl[row * 17 + ch] = srcL[idx];
        }
    }
    __syncthreads();

    int wid = tid >> 5, lane = tid & 31;
    int warp_m = (wid & 1) * 32, warp_n = (wid >> 1) * 32;
    unsigned baseAh = smem_u32p(sAh), baseAl = smem_u32p(sAl);
    unsigned baseBh = smem_u32p(sBh), baseBl = smem_u32p(sBl);
    int arow = warp_m + (lane & 15);
    int kofa = (lane >> 4) * 8;
    int brow = warp_n + (lane & 7);
    int kofb = ((lane >> 3) & 1) * 8;

    float acc[2][4][4];
    #pragma unroll
    for (int mi = 0; mi < 2; mi++)
        #pragma unroll
        for (int ni = 0; ni < 4; ni++)
            #pragma unroll
            for (int c = 0; c < 4; c++) acc[mi][ni][c] = 0.0f;

    #pragma unroll
    for (int ks = 0; ks < 8; ks++) {
        unsigned ah[2][4], al[2][4], bh[4][2], bl[4][2];
        #pragma unroll
        for (int mi = 0; mi < 2; mi++) {
            unsigned ao = (unsigned)((arow + mi * 16) * 272 + (ks * 16 + kofa) * 2);
            ldmx4(ah[mi], baseAh + ao);
            ldmx4(al[mi], baseAl + ao);
        }
        #pragma unroll
        for (int ni = 0; ni < 4; ni++) {
            unsigned bo = (unsigned)((brow + ni * 8) * 272 + (ks * 16 + kofb) * 2);
            ldmx2(bh[ni], baseBh + bo);
            ldmx2(bl[ni], baseBl + bo);
        }
        #pragma unroll
        for (int mi = 0; mi < 2; mi++)
            #pragma unroll
            for (int ni = 0; ni < 4; ni++) {
                mma16816(acc[mi][ni], ah[mi], bh[ni]);
                mma16816(acc[mi][ni], ah[mi], bl[ni]);
                mma16816(acc[mi][ni], al[mi], bh[ni]);
            }
    }

    #pragma unroll
    for (int mi = 0; mi < 2; mi++)
        #pragma unroll
        for (int ni = 0; ni < 4; ni++) {
            int row = bm0 + warp_m + mi * 16 + (lane >> 2);
            int col = bn0 + warp_n + ni * 8 + (lane & 3) * 2;
            if (MODE == 1) {
                float b0 = g_Bcat[col], b1 = g_Bcat[col + 1];
                *(float2*)&g_P[(size_t)row * 512 + col] =
                    make_float2(acc[mi][ni][0] + b0, acc[mi][ni][1] + b1);
                *(float2*)&g_P[(size_t)(row + 8) * 512 + col] =
                    make_float2(acc[mi][ni][2] + b0, acc[mi][ni][3] + b1);
            } else {
                float b0 = obias[col], b1 = obias[col + 1];
                float m0 = (float)mask[row], m1 = (float)mask[row + 8];
                *(float2*)&Cout[(size_t)row * 128 + col] =
                    make_float2((acc[mi][ni][0] + b0) * m0, (acc[mi][ni][1] + b1) * m0);
                *(float2*)&Cout[(size_t)(row + 8) * 128 + col] =
                    make_float2((acc[mi][ni][2] + b0) * m1, (acc[mi][ni][3] + b1) * m1);
            }
        }
}

// ---------------- K3: attn — cp.async pipelined, 2 CTAs/SM (smem trimmed) ----------------
// grid (256 rows, 4 heads), 256 threads, dyn smem 114816 B (<=115200 -> 2 CTAs/SM).
// floats: R1  @0     [9216]: kf[128][66] | kvp[2][4][1024]+ksp[256] | g/out [256][36]
//         R2a @9216  [4608]: k [128][36]; later kv[2048]+ks[64]
//         R2b @13824 [4608]: v [128][36]   (mask NOT applied to v: kf carries it, mask in {0,1})
//         s_q @18432 [9216]: q [256][36]
//         s_w @27648 [1056]
// (mask read directly from pm[] in the features phase — no smem copy)
__global__ void __launch_bounds__(256, 2) attn_kernel(const int*   __restrict__ pm,
                                                      const float* __restrict__ qfw,
                                                      const float* __restrict__ qfb,
                                                      const float* __restrict__ kfw,
                                                      const float* __restrict__ kfb) {
    extern __shared__ float sm[];
    float* R1     = sm;             // 9216
    float* R2a    = sm + 9216;      // 4608
    float* R2b    = sm + 13824;     // 4608
    float* s_q    = sm + 18432;     // 9216
    float* s_w    = sm + 27648;     // 1056

    unsigned R1u  = smem_u32p(R1);
    unsigned R2au = smem_u32p(R2a);
    unsigned R2bu = smem_u32p(R2b);
    unsigned squ  = smem_u32p(s_q);

    int tid = threadIdx.x;
    int r = blockIdx.x, h = blockIdx.y;
    int t0 = r * 256;
    int lane = tid & 31, w = tid >> 5;

    // ---- prologue: issue k chunk0 + full q via cp.async ----
    {
        const float* Pk0 = g_P + (size_t)t0 * 512 + 128 + h * 32;
        #pragma unroll
        for (int it = 0; it < 4; it++) {
            int idx = it * 256 + tid;
            int token = idx >> 3, c4 = idx & 7;
            cpasync16(R2au + (unsigned)(token * 36 + c4 * 4) * 4,
                      Pk0 + (size_t)token * 512 + c4 * 4);
        }
        CP_COMMIT();
        const float* Pq0 = g_P + (size_t)t0 * 512 + h * 32;
        #pragma unroll
        for (int it = 0; it < 8; it++) {
            int idx = it * 256 + tid;
            int token = idx >> 3, c4 = idx & 7;
            cpasync16(squ + (unsigned)(token * 36 + c4 * 4) * 4,
                      Pq0 + (size_t)token * 512 + c4 * 4);
        }
        CP_COMMIT();
    }

    for (int i = tid; i < 1024; i += 256) s_w[i] = kfw[i];
    if (tid < 32) s_w[1024 + tid] = kfb[tid];

    // step-B decomposition: warp = (fhalf, tgroup); lane = (fy, dx); 4f x 8d per lane
    int fhalf = w & 1, tg = w >> 1;
    int fy = lane >> 2, dx = lane & 3;
    int fbase = fhalf * 32 + fy * 4;
    u64 acc2[4][4];
    float ks[4];
    #pragma unroll
    for (int j = 0; j < 4; j++) {
        ks[j] = 0.0f;
        #pragma unroll
        for (int q = 0; q < 4; q++) acc2[j][q] = 0ull;
    }

    #pragma unroll 1
    for (int c = 0; c < 2; c++) {
        if (c == 0) { CP_WAIT(1); } else { CP_WAIT(0); }   // current k chunk ready
        __syncthreads();
        // issue v chunk c (pure copy — no mask; kf carries the 0/1 mask)
        {
            const float* Pv = g_P + (size_t)(t0 + c * 128) * 512 + 256 + h * 32;
            #pragma unroll
            for (int it = 0; it < 4; it++) {
                int idx = it * 256 + tid;
                int token = idx >> 3, c4 = idx & 7;
                cpasync16(R2bu + (unsigned)(token * 36 + c4 * 4) * 4,
                          Pv + (size_t)token * 512 + c4 * 4);
            }
            CP_COMMIT();
        }
        // ---- features: thread -> (token = tid&127, rows hh*16..+15) ----
        {
            int tk = tid & 127, hh = tid >> 7;
            float mk = (float)pm[t0 + c * 128 + tk];
            const ulonglong2* kp = (const ulonglong2*)(R2a + tk * 36);
            u64 k2[16];
            #pragma unroll
            for (int i = 0; i < 8; i++) {
                ulonglong2 kk = kp[i];
                k2[2 * i] = kk.x; k2[2 * i + 1] = kk.y;
            }
            #pragma unroll
            for (int rr = 0; rr < 16; rr++) {
                int row = hh * 16 + rr;
                const u64* wr = (const u64*)&s_w[row * 32];   // broadcast LDS.64
                u64 a2 = 0ull, b2 = 0ull;
                #pragma unroll
                for (int dp = 0; dp < 8; dp++) {
                    ffma2(a2, wr[2 * dp],     k2[2 * dp]);
                    ffma2(b2, wr[2 * dp + 1], k2[2 * dp + 1]);
                }
                float2 fa = funpk(a2), fb = funpk(b2);
                float m = (fa.x + fa.y) + (fb.x + fb.y) + s_w[1024 + row];
                m = fminf(8.0f, fmaxf(-8.0f, m));
                R1[tk * 66 + row]      = __expf(m)  * mk;
                R1[tk * 66 + 32 + row] = __expf(-m) * mk;
            }
        }
        __syncthreads();   // features done reading R2a (k)
        if (c == 0) {
            // issue k chunk1 into R2a
            const float* Pk1 = g_P + (size_t)(t0 + 128) * 512 + 128 + h * 32;
            #pragma unroll
            for (int it = 0; it < 4; it++) {
                int idx = it * 256 + tid;
                int token = idx >> 3, c4 = idx & 7;
                cpasync16(R2au + (unsigned)(token * 36 + c4 * 4) * 4,
                          Pk1 + (size_t)token * 512 + c4 * 4);
            }
            CP_COMMIT();
            CP_WAIT(1);    // q + v0 done; k1 in flight
        } else {
            CP_WAIT(0);    // v1 done
        }
        __syncthreads();
        // ---- step B: 32 tokens per warp per chunk ----
        #pragma unroll 2
        for (int i = 0; i < 32; i++) {
            int nn = tg * 32 + i;
            float2 kfa  = *(const float2*)&R1[nn * 66 + fbase];
            float2 kfb2 = *(const float2*)&R1[nn * 66 + fbase + 2];
            u64 kf2[4];
            kf2[0] = frep2(kfa.x);  kf2[1] = frep2(kfa.y);
            kf2[2] = frep2(kfb2.x); kf2[3] = frep2(kfb2.y);
            const ulonglong2* vmp = (const ulonglong2*)(R2b + nn * 36 + dx * 8);
            ulonglong2 v0 = vmp[0], v1 = vmp[1];
            u64 vm2[4] = {v0.x, v0.y, v1.x, v1.y};
            #pragma unroll
            for (int j = 0; j < 4; j++)
                #pragma unroll
                for (int q = 0; q < 4; q++) ffma2(acc2[j][q], kf2[j], vm2[q]);
            if (dx == 0) {
                ks[0] += kfa.x; ks[1] += kfa.y; ks[2] += kfb2.x; ks[3] += kfb2.y;
            }
        }
        __syncthreads();   // step B done reading R1 (kf) / R2b (v)
    }

    // ---- spill partials into R1: kvp[2][4][1024] + ksp[256] ----
    float* kvp = R1;
    float* ksp = R1 + 8192;
    #pragma unroll
    for (int j = 0; j < 4; j++) {
        float2 u0 = funpk(acc2[j][0]), u1 = funpk(acc2[j][1]);
        float2 u2 = funpk(acc2[j][2]), u3 = funpk(acc2[j][3]);
        float* dst = &kvp[fhalf * 4096 + tg * 1024 + (fy * 4 + j) * 32 + dx * 8];
        *(float4*)dst       = make_float4(u0.x, u0.y, u1.x, u1.y);
        *(float4*)(dst + 4) = make_float4(u2.x, u2.y, u3.x, u3.y);
    }
    if (dx == 0) {
        #pragma unroll
        for (int j = 0; j < 4; j++) ksp[fhalf * 128 + tg * 32 + fy * 4 + j] = ks[j];
    }
    for (int i = tid; i < 1024; i += 256) s_w[i] = qfw[i];
    if (tid < 32) s_w[1024 + tid] = qfb[tid];
    __syncthreads();

    // ---- reduce 4 copies -> s_kv[2048] + s_ks[64] in R2a (k space free) ----
    float* s_kv = R2a;
    float* s_ks = R2a + 2048;
    {
        int e = tid * 8;
        int f = e >> 5, d0 = e & 31;
        const float* src = &kvp[(f >> 5) * 4096 + (f & 31) * 32 + d0];
        float4 r0 = make_float4(0, 0, 0, 0), r1 = make_float4(0, 0, 0, 0);
        #pragma unroll
        for (int c2 = 0; c2 < 4; c2++) {
            float4 p0 = *(const float4*)(src + c2 * 1024);
            float4 p1 = *(const float4*)(src + c2 * 1024 + 4);
            r0.x += p0.x; r0.y += p0.y; r0.z += p0.z; r0.w += p0.w;
            r1.x += p1.x; r1.y += p1.y; r1.z += p1.z; r1.w += p1.w;
        }
        *(float4*)&s_kv[e]     = r0;
        *(float4*)&s_kv[e + 4] = r1;
        if (tid < 64) {
            float s = 0.0f;
            #pragma unroll
            for (int c2 = 0; c2 < 4; c2++) s += ksp[(tid >> 5) * 128 + c2 * 32 + (tid & 31)];
            s_ks[tid] = s;
        }
    }
    __syncthreads();

    // ---- issue g via cp.async into R1 [256][36] (kvp consumed); step C hides it ----
    {
        const float* Pg0 = g_P + (size_t)t0 * 512 + 384 + h * 32;
        #pragma unroll
        for (int it = 0; it < 8; it++) {
            int idx = it * 256 + tid;
            int token = idx >> 3, c4 = idx & 7;
            cpasync16(R1u + (unsigned)(token * 36 + c4 * 4) * 4,
                      Pg0 + (size_t)token * 512 + c4 * 4);
        }
        CP_COMMIT();
    }

    // ---- step C: qf features (q from s_q), num/den ----
    u64 num2[16];
    #pragma unroll
    for (int q = 0; q < 16; q++) num2[q] = 0ull;
    float den = 0.0f;
    {
        const ulonglong2* qp = (const ulonglong2*)(s_q + tid * 36);
        u64 q2[16];
        #pragma unroll
        for (int i = 0; i < 8; i++) {
            ulonglong2 qq = qp[i];
            q2[2 * i] = qq.x; q2[2 * i + 1] = qq.y;
        }
        #pragma unroll 4
        for (int row = 0; row < 32; row++) {
            const u64* wr = (const u64*)&s_w[row * 32];   // broadcast LDS.64
            u64 a2 = 0ull, b2 = 0ull;
            #pragma unroll
            for (int dp = 0; dp < 8; dp++) {
                ffma2(a2, wr[2 * dp],     q2[2 * dp]);
                ffma2(b2, wr[2 * dp + 1], q2[2 * dp + 1]);
            }
            float2 fa = funpk(a2), fb = funpk(b2);
            float m = (fa.x + fa.y) + (fb.x + fb.y) + s_w[1024 + row];
            m = fminf(8.0f, fmaxf(-8.0f, m));
            float e  = __expf(m);
            float ei = __expf(-m);
            den += e  * s_ks[row];
            den += ei * s_ks[row + 32];
            u64 e2 = frep2(e), ei2 = frep2(ei);
            const ulonglong2* k1 = (const ulonglong2*)&s_kv[row * 32];
            const ulonglong2* k2 = (const ulonglong2*)&s_kv[(row + 32) * 32];
            #pragma unroll
            for (int q = 0; q < 8; q++) {
                ulonglong2 ka = k1[q];
                ffma2(num2[2 * q],     e2, ka.x);
                ffma2(num2[2 * q + 1], e2, ka.y);
            }
            #pragma unroll
            for (int q = 0; q < 8; q++) {
                ulonglong2 kb = k2[q];
                ffma2(num2[2 * q],     ei2, kb.x);
                ffma2(num2[2 * q + 1], ei2, kb.y);
            }
        }
    }
    den = fmaxf(den, 1e-6f);
    float inv = 1.0f / den;
    CP_WAIT(0);        // g landed
    __syncthreads();

    // ---- gate in place (R1 stride 36), coop store ----
    {
        float* grow = R1 + tid * 36;
        #pragma unroll
        for (int i = 0; i < 8; i++) {
            float2 ua = funpk(num2[2 * i]);
            float2 ub = funpk(num2[2 * i + 1]);
            float4 gv = *(float4*)(grow + 4 * i);
            float4 o;
            o.x = __fdividef(1.0f, 1.0f + __expf(-gv.x)) * ua.x * inv;
            o.y = __fdividef(1.0f, 1.0f + __expf(-gv.y)) * ua.y * inv;
            o.z = __fdividef(1.0f, 1.0f + __expf(-gv.z)) * ub.x * inv;
            o.w = __fdividef(1.0f, 1.0f + __expf(-gv.w)) * ub.y * inv;
            *(float4*)(grow + 4 * i) = o;
        }
    }
    __syncthreads();
    {
        float* GA0 = g_GA + (size_t)t0 * 128 + h * 32;
        #pragma unroll
        for (int it = 0; it < 8; it++) {
            int idx = it * 256 + tid;
            int token = idx >> 3, c4 = idx & 7;
            float4 o = *(const float4*)(R1 + token * 36 + c4 * 4);
            *(float4*)(GA0 + (size_t)token * 128 + c4 * 4) = o;
        }
    }
}

// ---------------- launcher ----------------
extern "C" void kernel_launch(void* const* d_in, const int* in_sizes, int n_in,
                              void* d_out, int out_size) {
    const float* z    = (const float*)d_in[0];
    const int*   pm   = (const int*)  d_in[1];
    const float* lnw  = (const float*)d_in[2];
    const float* lnb  = (const float*)d_in[3];
    const float* qw   = (const float*)d_in[4];
    const float* qb   = (const float*)d_in[5];
    const float* kw   = (const float*)d_in[6];
    const float* kb   = (const float*)d_in[7];
    const float* vw   = (const float*)d_in[8];
    const float* vb   = (const float*)d_in[9];
    const float* qfw  = (const float*)d_in[10];
    const float* qfb  = (const float*)d_in[11];
    const float* kfw  = (const float*)d_in[12];
    const float* kfb  = (const float*)d_in[13];
    const float* gw   = (const float*)d_in[14];
    const float* gb   = (const float*)d_in[15];
    const float* ow   = (const float*)d_in[16];
    const float* ob   = (const float*)d_in[17];
    float* out = (float*)d_out;

    static int attr_set = 0;
    if (!attr_set) {
        cudaFuncSetAttribute(attn_kernel, cudaFuncAttributeMaxDynamicSharedMemorySize, 114816);
        cudaFuncSetAttribute(mma_gemm<1>, cudaFuncAttributeMaxDynamicSharedMemorySize, 104448);
        cudaFuncSetAttribute(mma_gemm<2>, cudaFuncAttributeMaxDynamicSharedMemorySize, 104448);
        attr_set = 1;
    }

    pack_kernel<<<320, 256>>>(qw, kw, vw, gw, qb, kb, vb, gb, ow);
    ln_kernel<<<8192, 256>>>(z, lnw, lnb);
    mma_gemm<1><<<dim3(1024, 4), 256, 104448>>>(nullptr, nullptr, nullptr);
    attn_kernel<<<dim3(256, 4), 256, 114816>>>(pm, qfw, qfb, kfw, kfb);
    mma_gemm<2><<<dim3(1024, 1), 256, 104448>>>(ob, pm, out);
}

// round 14
// speedup vs baseline: 1.0952x; 1.0035x over previous
#include <cuda_runtime.h>
#include <cuda_bf16.h>

// ---------------- scratch (static device memory; no allocation) ----------------
__device__ float         g_P [65536ull * 512];   // q|k|v|g projections (row-major)
__device__ float         g_GA[65536ull * 128];   // gate * attn_out (row-major)
__device__ __nv_bfloat16 g_znh[8388608];          // layernormed z hi [token][128]
__device__ __nv_bfloat16 g_znl[8388608];          // layernormed z lo
__device__ __nv_bfloat16 g_Wh[65536], g_Wl[65536];   // packed q|k|v|g weights [512][128]
__device__ __nv_bfloat16 g_Oh[16384], g_Ol[16384];   // o_w [128][128]
__device__ float         g_Bcat[512];                 // packed q|k|v|g biases

typedef unsigned long long u64;

// ---------------- f32x2 packed-FMA helpers ----------------
__device__ __forceinline__ u64 frep2(float x) {
    u64 r; asm("mov.b64 %0, {%1, %1};" : "=l"(r) : "f"(x)); return r;
}
__device__ __forceinline__ void ffma2(u64& d, u64 a, u64 b) {
    asm("fma.rn.f32x2 %0, %1, %2, %0;" : "+l"(d) : "l"(a), "l"(b));
}
__device__ __forceinline__ float2 funpk(u64 d) {
    float2 f; asm("mov.b64 {%0, %1}, %2;" : "=f"(f.x), "=f"(f.y) : "l"(d)); return f;
}

// ---------------- cp.async helpers ----------------
__device__ __forceinline__ void cpasync16(unsigned dst, const void* src) {
    asm volatile("cp.async.cg.shared.global [%0], [%1], 16;" :: "r"(dst), "l"(src));
}
#define CP_COMMIT() asm volatile("cp.async.commit_group;" ::: "memory")
#define CP_WAIT(n)  asm volatile("cp.async.wait_group %0;" :: "n"(n) : "memory")

// ---------------- tensor-core helpers ----------------
__device__ __forceinline__ unsigned smem_u32p(const void* p) {
    return (unsigned)__cvta_generic_to_shared(p);
}
__device__ __forceinline__ void ldmx4(unsigned* r, unsigned addr) {
    asm volatile("ldmatrix.sync.aligned.m8n8.x4.shared.b16 {%0,%1,%2,%3}, [%4];"
        : "=r"(r[0]), "=r"(r[1]), "=r"(r[2]), "=r"(r[3]) : "r"(addr));
}
__device__ __forceinline__ void ldmx2(unsigned* r, unsigned addr) {
    asm volatile("ldmatrix.sync.aligned.m8n8.x2.shared.b16 {%0,%1}, [%2];"
        : "=r"(r[0]), "=r"(r[1]) : "r"(addr));
}
__device__ __forceinline__ void mma16816(float* c, const unsigned* a, const unsigned* b) {
    asm volatile("mma.sync.aligned.m16n8k16.row.col.f32.bf16.bf16.f32 "
        "{%0,%1,%2,%3}, {%4,%5,%6,%7}, {%8,%9}, {%0,%1,%2,%3};"
        : "+f"(c[0]), "+f"(c[1]), "+f"(c[2]), "+f"(c[3])
        : "r"(a[0]), "r"(a[1]), "r"(a[2]), "r"(a[3]), "r"(b[0]), "r"(b[1]));
}
__device__ __forceinline__ void bf16split(float x, __nv_bfloat16& h, __nv_bfloat16& l) {
    h = __float2bfloat16_rn(x);
    l = __float2bfloat16_rn(x - __bfloat162float(h));
}

// ---------------- K0: pack + split weights ----------------
__global__ void pack_kernel(const float* __restrict__ qw, const float* __restrict__ kw,
                            const float* __restrict__ vw, const float* __restrict__ gw,
                            const float* __restrict__ qb, const float* __restrict__ kb,
                            const float* __restrict__ vb, const float* __restrict__ gb,
                            const float* __restrict__ ow) {
    int idx = blockIdx.x * 256 + threadIdx.x;   // 0 .. 81919
    if (idx < 65536) {
        int row = idx >> 7, col = idx & 127;
        const float* w = (row < 128) ? qw : (row < 256) ? kw : (row < 384) ? vw : gw;
        float x = w[(row & 127) * 128 + col];
        __nv_bfloat16 h, l; bf16split(x, h, l);
        g_Wh[idx] = h; g_Wl[idx] = l;
        if (idx < 512) {
            const float* b = (idx < 128) ? qb : (idx < 256) ? kb : (idx < 384) ? vb : gb;
            g_Bcat[idx] = b[idx & 127];
        }
    } else if (idx < 81920) {
        int i = idx - 65536;
        __nv_bfloat16 h, l; bf16split(ow[i], h, l);
        g_Oh[i] = h; g_Ol[i] = l;
    }
}

// ---------------- K1: LayerNorm -> bf16 hi/lo ----------------
__global__ void ln_kernel(const float* __restrict__ z,
                          const float* __restrict__ lw,
                          const float* __restrict__ lb) {
    int warp = threadIdx.x >> 5, lane = threadIdx.x & 31;
    int t = blockIdx.x * 8 + warp;
    const float4* zp = (const float4*)(z + (size_t)t * 128);
    float4 v = zp[lane];
    float s = v.x + v.y + v.z + v.w;
    float q = v.x * v.x + v.y * v.y + v.z * v.z + v.w * v.w;
    #pragma unroll
    for (int o = 16; o; o >>= 1) {
        s += __shfl_xor_sync(0xFFFFFFFFu, s, o);
        q += __shfl_xor_sync(0xFFFFFFFFu, q, o);
    }
    float mu  = s * (1.0f / 128.0f);
    float var = q * (1.0f / 128.0f) - mu * mu;
    float rs  = rsqrtf(var + 1e-5f);
    float4 w4 = ((const float4*)lw)[lane];
    float4 b4 = ((const float4*)lb)[lane];
    float o4[4];
    o4[0] = (v.x - mu) * rs * w4.x + b4.x;
    o4[1] = (v.y - mu) * rs * w4.y + b4.y;
    o4[2] = (v.z - mu) * rs * w4.z + b4.z;
    o4[3] = (v.w - mu) * rs * w4.w + b4.w;
    __nv_bfloat16 h[4], l[4];
    #pragma unroll
    for (int i = 0; i < 4; i++) bf16split(o4[i], h[i], l[i]);
    size_t base = (size_t)t * 128 + lane * 4;
    *(__nv_bfloat162*)(g_znh + base)     = __nv_bfloat162(h[0], h[1]);
    *(__nv_bfloat162*)(g_znh + base + 2) = __nv_bfloat162(h[2], h[3]);
    *(__nv_bfloat162*)(g_znl + base)     = __nv_bfloat162(l[0], l[1]);
    *(__nv_bfloat162*)(g_znl + base + 2) = __nv_bfloat162(l[2], l[3]);
}

// ---------------- K2: pipelined proj GEMM (cp.async double-buffered, BK=32) ----------------
// C[m][n] = sum_k zn[m][k]*W[n][k] + Bcat[n] -> g_P.  CTA tile 64x128, 8 warps 32x32.
// smem per buffer (bf16, row stride 40): Ah@0[64*40] Al@2560 Bh@5120[128*40] Bl@10240
// buffer size 15360 bf16 = 30720 B; x2 buffers = 61440 B -> 3 CTAs/SM.
__global__ void __launch_bounds__(256, 3) gemm_proj(void) {
    extern __shared__ __nv_bfloat16 smem[];
    const int BUF = 15360;
    int tid = threadIdx.x;
    int bm0 = blockIdx.x * 64;
    int bn0 = blockIdx.y * 128;

    int wid = tid >> 5, lane = tid & 31;
    int warp_m = (wid & 1) * 32, warp_n = (wid >> 1) * 32;
    int arow = warp_m + (lane & 15);
    int kofa = (lane >> 4) * 8;
    int brow = warp_n + (lane & 7);
    int kofb = ((lane >> 3) & 1) * 8;

    // ---- stage loader: 1536 cp.async16 tasks over 256 threads ----
    auto load_stage = [&](int ks, int buf) {
        unsigned baseu = smem_u32p(smem + buf * BUF);
        #pragma unroll
        for (int it = 0; it < 6; it++) {
            int t = it * 256 + tid;
            int i = t & 511;
            int row = i >> 2, ch = i & 3;
            if (t < 256) {
                cpasync16(baseu + (unsigned)(row * 40 + ch * 8) * 2,
                          g_znh + (size_t)(bm0 + row) * 128 + ks + ch * 8);
            } else if (t < 512) {
                cpasync16(baseu + (unsigned)(2560 + (row - 64) * 40 + ch * 8) * 2,
                          g_znl + (size_t)(bm0 + row - 64) * 128 + ks + ch * 8);
            } else if (t < 1024) {
                cpasync16(baseu + (unsigned)(5120 + row * 40 + ch * 8) * 2,
                          g_Wh + (size_t)(bn0 + row) * 128 + ks + ch * 8);
            } else {
                // t in 1024..1535: i = t & 511 already reduces row to 0..127
                cpasync16(baseu + (unsigned)(10240 + row * 40 + ch * 8) * 2,
                          g_Wl + (size_t)(bn0 + row) * 128 + ks + ch * 8);
            }
        }
        CP_COMMIT();
    };

    load_stage(0, 0);

    float acc[2][4][4];
    #pragma unroll
    for (int mi = 0; mi < 2; mi++)
        #pragma unroll
        for (int ni = 0; ni < 4; ni++)
            #pragma unroll
            for (int c = 0; c < 4; c++) acc[mi][ni][c] = 0.0f;

    #pragma unroll
    for (int s = 0; s < 4; s++) {
        if (s < 3) { load_stage((s + 1) * 32, (s + 1) & 1); CP_WAIT(1); }
        else       { CP_WAIT(0); }
        __syncthreads();
        unsigned bAh = smem_u32p(smem + (s & 1) * BUF);
        unsigned bAl = bAh + 2560 * 2;
        unsigned bBh = bAh + 5120 * 2;
        unsigned bBl = bAh + 10240 * 2;
        #pragma unroll
        for (int kk = 0; kk < 2; kk++) {
            unsigned ah[2][4], al[2][4], bh[4][2], bl[4][2];
            #pragma unroll
            for (int mi = 0; mi < 2; mi++) {
                unsigned ao = (unsigned)((arow + mi * 16) * 80 + (kk * 16 + kofa) * 2);
                ldmx4(ah[mi], bAh + ao);
                ldmx4(al[mi], bAl + ao);
            }
            #pragma unroll
            for (int ni = 0; ni < 4; ni++) {
                unsigned bo = (unsigned)((brow + ni * 8) * 80 + (kk * 16 + kofb) * 2);
                ldmx2(bh[ni], bBh + bo);
                ldmx2(bl[ni], bBl + bo);
            }
            #pragma unroll
            for (int mi = 0; mi < 2; mi++)
                #pragma unroll
                for (int ni = 0; ni < 4; ni++) {
                    mma16816(acc[mi][ni], ah[mi], bh[ni]);
                    mma16816(acc[mi][ni], ah[mi], bl[ni]);
                    mma16816(acc[mi][ni], al[mi], bh[ni]);
                }
        }
        __syncthreads();   // readers done before buffer reuse
    }

    // ---- epilogue: bias + store to g_P ----
    #pragma unroll
    for (int mi = 0; mi < 2; mi++)
        #pragma unroll
        for (int ni = 0; ni < 4; ni++) {
            int row = bm0 + warp_m + mi * 16 + (lane >> 2);
            int col = bn0 + warp_n + ni * 8 + (lane & 3) * 2;
            float b0 = g_Bcat[col], b1 = g_Bcat[col + 1];
            *(float2*)&g_P[(size_t)row * 512 + col] =
                make_float2(acc[mi][ni][0] + b0, acc[mi][ni][1] + b1);
            *(float2*)&g_P[(size_t)(row + 8) * 512 + col] =
                make_float2(acc[mi][ni][2] + b0, acc[mi][ni][3] + b1);
        }
}

// ---------------- K4: output GEMM ----------------
__global__ void __launch_bounds__(256, 2) mma_gemm2(const float* __restrict__ obias,
                                                    const int*   __restrict__ mask,
                                                    float* __restrict__ Cout) {
    extern __shared__ __nv_bfloat16 smem[];
    __nv_bfloat16* sAh = smem;             // 64*136
    __nv_bfloat16* sAl = smem + 8704;
    __nv_bfloat16* sBh = smem + 17408;     // 128*136
    __nv_bfloat16* sBl = smem + 34816;
    int tid = threadIdx.x;
    int bm0 = blockIdx.x * 64;

    {
        const float4* srcA = (const float4*)(g_GA + (size_t)bm0 * 128);
        #pragma unroll
        for (int it = 0; it < 8; it++) {
            int idx = it * 256 + tid;
            int row = idx >> 5, c4 = idx & 31;
            float4 v = srcA[idx];
            int col = c4 * 4;
            __nv_bfloat16 h, l;
            bf16split(v.x, h, l); sAh[row * 136 + col]     = h; sAl[row * 136 + col]     = l;
            bf16split(v.y, h, l); sAh[row * 136 + col + 1] = h; sAl[row * 136 + col + 1] = l;
            bf16split(v.z, h, l); sAh[row * 136 + col + 2] = h; sAl[row * 136 + col + 2] = l;
            bf16split(v.w, h, l); sAh[row * 136 + col + 3] = h; sAl[row * 136 + col + 3] = l;
        }
    }
    {
        const uint4* srcH = (const uint4*)(g_Oh);
        const uint4* srcL = (const uint4*)(g_Ol);
        uint4* dBh = (uint4*)sBh; uint4* dBl = (uint4*)sBl;
        #pragma unroll
        for (int it = 0; it < 8; it++) {
            int idx = it * 256 + tid;
            int row = idx >> 4, ch = idx & 15;
            dBh[row * 17 + ch] = srcH[idx];
            dBl[row * 17 + ch] = srcL[idx];
        }
    }
    __syncthreads();

    int wid = tid >> 5, lane = tid & 31;
    int warp_m = (wid & 1) * 32, warp_n = (wid >> 1) * 32;
    unsigned baseAh = smem_u32p(sAh), baseAl = smem_u32p(sAl);
    unsigned baseBh = smem_u32p(sBh), baseBl = smem_u32p(sBl);
    int arow = warp_m + (lane & 15);
    int kofa = (lane >> 4) * 8;
    int brow = warp_n + (lane & 7);
    int kofb = ((lane >> 3) & 1) * 8;

    float acc[2][4][4];
    #pragma unroll
    for (int mi = 0; mi < 2; mi++)
        #pragma unroll
        for (int ni = 0; ni < 4; ni++)
            #pragma unroll
            for (int c = 0; c < 4; c++) acc[mi][ni][c] = 0.0f;

    #pragma unroll
    for (int ks = 0; ks < 8; ks++) {
        unsigned ah[2][4], al[2][4], bh[4][2], bl[4][2];
        #pragma unroll
        for (int mi = 0; mi < 2; mi++) {
            unsigned ao = (unsigned)((arow + mi * 16) * 272 + (ks * 16 + kofa) * 2);
            ldmx4(ah[mi], baseAh + ao);
            ldmx4(al[mi], baseAl + ao);
        }
        #pragma unroll
        for (int ni = 0; ni < 4; ni++) {
            unsigned bo = (unsigned)((brow + ni * 8) * 272 + (ks * 16 + kofb) * 2);
            ldmx2(bh[ni], baseBh + bo);
            ldmx2(bl[ni], baseBl + bo);
        }
        #pragma unroll
        for (int mi = 0; mi < 2; mi++)
            #pragma unroll
            for (int ni = 0; ni < 4; ni++) {
                mma16816(acc[mi][ni], ah[mi], bh[ni]);
                mma16816(acc[mi][ni], ah[mi], bl[ni]);
                mma16816(acc[mi][ni], al[mi], bh[ni]);
            }
    }

    #pragma unroll
    for (int mi = 0; mi < 2; mi++)
        #pragma unroll
        for (int ni = 0; ni < 4; ni++) {
            int row = bm0 + warp_m + mi * 16 + (lane >> 2);
            int col = warp_n + ni * 8 + (lane & 3) * 2;
            float b0 = obias[col], b1 = obias[col + 1];
            float m0 = (float)mask[row], m1 = (float)mask[row + 8];
            *(float2*)&Cout[(size_t)row * 128 + col] =
                make_float2((acc[mi][ni][0] + b0) * m0, (acc[mi][ni][1] + b1) * m0);
            *(float2*)&Cout[(size_t)(row + 8) * 128 + col] =
                make_float2((acc[mi][ni][2] + b0) * m1, (acc[mi][ni][3] + b1) * m1);
        }
}

// ---------------- K3: attn — cp.async pipelined, 2 CTAs/SM (round-12 verbatim) ----------------
__global__ void __launch_bounds__(256, 2) attn_kernel(const int*   __restrict__ pm,
                                                      const float* __restrict__ qfw,
                                                      const float* __restrict__ qfb,
                                                      const float* __restrict__ kfw,
                                                      const float* __restrict__ kfb) {
    extern __shared__ float sm[];
    float* R1     = sm;             // 9216
    float* R2a    = sm + 9216;      // 4608
    float* R2b    = sm + 13824;     // 4608
    float* s_q    = sm + 18432;     // 9216
    float* s_w    = sm + 27648;     // 1056

    unsigned R1u  = smem_u32p(R1);
    unsigned R2au = smem_u32p(R2a);
    unsigned R2bu = smem_u32p(R2b);
    unsigned squ  = smem_u32p(s_q);

    int tid = threadIdx.x;
    int r = blockIdx.x, h = blockIdx.y;
    int t0 = r * 256;
    int lane = tid & 31, w = tid >> 5;

    {
        const float* Pk0 = g_P + (size_t)t0 * 512 + 128 + h * 32;
        #pragma unroll
        for (int it = 0; it < 4; it++) {
            int idx = it * 256 + tid;
            int token = idx >> 3, c4 = idx & 7;
            cpasync16(R2au + (unsigned)(token * 36 + c4 * 4) * 4,
                      Pk0 + (size_t)token * 512 + c4 * 4);
        }
        CP_COMMIT();
        const float* Pq0 = g_P + (size_t)t0 * 512 + h * 32;
        #pragma unroll
        for (int it = 0; it < 8; it++) {
            int idx = it * 256 + tid;
            int token = idx >> 3, c4 = idx & 7;
            cpasync16(squ + (unsigned)(token * 36 + c4 * 4) * 4,
                      Pq0 + (size_t)token * 512 + c4 * 4);
        }
        CP_COMMIT();
    }

    for (int i = tid; i < 1024; i += 256) s_w[i] = kfw[i];
    if (tid < 32) s_w[1024 + tid] = kfb[tid];

    int fhalf = w & 1, tg = w >> 1;
    int fy = lane >> 2, dx = lane & 3;
    int fbase = fhalf * 32 + fy * 4;
    u64 acc2[4][4];
    float ks[4];
    #pragma unroll
    for (int j = 0; j < 4; j++) {
        ks[j] = 0.0f;
        #pragma unroll
        for (int q = 0; q < 4; q++) acc2[j][q] = 0ull;
    }

    #pragma unroll 1
    for (int c = 0; c < 2; c++) {
        if (c == 0) { CP_WAIT(1); } else { CP_WAIT(0); }
        __syncthreads();
        {
            const float* Pv = g_P + (size_t)(t0 + c * 128) * 512 + 256 + h * 32;
            #pragma unroll
            for (int it = 0; it < 4; it++) {
                int idx = it * 256 + tid;
                int token = idx >> 3, c4 = idx & 7;
                cpasync16(R2bu + (unsigned)(token * 36 + c4 * 4) * 4,
                          Pv + (size_t)token * 512 + c4 * 4);
            }
            CP_COMMIT();
        }
        {
            int tk = tid & 127, hh = tid >> 7;
            float mk = (float)pm[t0 + c * 128 + tk];
            const ulonglong2* kp = (const ulonglong2*)(R2a + tk * 36);
            u64 k2[16];
            #pragma unroll
            for (int i = 0; i < 8; i++) {
                ulonglong2 kk = kp[i];
                k2[2 * i] = kk.x; k2[2 * i + 1] = kk.y;
            }
            #pragma unroll
            for (int rr = 0; rr < 16; rr++) {
                int row = hh * 16 + rr;
                const u64* wr = (const u64*)&s_w[row * 32];
                u64 a2 = 0ull, b2 = 0ull;
                #pragma unroll
                for (int dp = 0; dp < 8; dp++) {
                    ffma2(a2, wr[2 * dp],     k2[2 * dp]);
                    ffma2(b2, wr[2 * dp + 1], k2[2 * dp + 1]);
                }
                float2 fa = funpk(a2), fb = funpk(b2);
                float m = (fa.x + fa.y) + (fb.x + fb.y) + s_w[1024 + row];
                m = fminf(8.0f, fmaxf(-8.0f, m));
                R1[tk * 66 + row]      = __expf(m)  * mk;
                R1[tk * 66 + 32 + row] = __expf(-m) * mk;
            }
        }
        __syncthreads();
        if (c == 0) {
            const float* Pk1 = g_P + (size_t)(t0 + 128) * 512 + 128 + h * 32;
            #pragma unroll
            for (int it = 0; it < 4; it++) {
                int idx = it * 256 + tid;
                int token = idx >> 3, c4 = idx & 7;
                cpasync16(R2au + (unsigned)(token * 36 + c4 * 4) * 4,
                          Pk1 + (size_t)token * 512 + c4 * 4);
            }
            CP_COMMIT();
            CP_WAIT(1);
        } else {
            CP_WAIT(0);
        }
        __syncthreads();
        #pragma unroll 2
        for (int i = 0; i < 32; i++) {
            int nn = tg * 32 + i;
            float2 kfa  = *(const float2*)&R1[nn * 66 + fbase];
            float2 kfb2 = *(const float2*)&R1[nn * 66 + fbase + 2];
            u64 kf2[4];
            kf2[0] = frep2(kfa.x);  kf2[1] = frep2(kfa.y);
            kf2[2] = frep2(kfb2.x); kf2[3] = frep2(kfb2.y);
            const ulonglong2* vmp = (const ulonglong2*)(R2b + nn * 36 + dx * 8);
            ulonglong2 v0 = vmp[0], v1 = vmp[1];
            u64 vm2[4] = {v0.x, v0.y, v1.x, v1.y};
            #pragma unroll
            for (int j = 0; j < 4; j++)
                #pragma unroll
                for (int q = 0; q < 4; q++) ffma2(acc2[j][q], kf2[j], vm2[q]);
            if (dx == 0) {
                ks[0] += kfa.x; ks[1] += kfa.y; ks[2] += kfb2.x; ks[3] += kfb2.y;
            }
        }
        __syncthreads();
    }

    float* kvp = R1;
    float* ksp = R1 + 8192;
    #pragma unroll
    for (int j = 0; j < 4; j++) {
        float2 u0 = funpk(acc2[j][0]), u1 = funpk(acc2[j][1]);
        float2 u2 = funpk(acc2[j][2]), u3 = funpk(acc2[j][3]);
        float* dst = &kvp[fhalf * 4096 + tg * 1024 + (fy * 4 + j) * 32 + dx * 8];
        *(float4*)dst       = make_float4(u0.x, u0.y, u1.x, u1.y);
        *(float4*)(dst + 4) = make_float4(u2.x, u2.y, u3.x, u3.y);
    }
    if (dx == 0) {
        #pragma unroll
        for (int j = 0; j < 4; j++) ksp[fhalf * 128 + tg * 32 + fy * 4 + j] = ks[j];
    }
    for (int i = tid; i < 1024; i += 256) s_w[i] = qfw[i];
    if (tid < 32) s_w[1024 + tid] = qfb[tid];
    __syncthreads();

    float* s_kv = R2a;
    float* s_ks = R2a + 2048;
    {
        int e = tid * 8;
        int f = e >> 5, d0 = e & 31;
        const float* src = &kvp[(f >> 5) * 4096 + (f & 31) * 32 + d0];
        float4 r0 = make_float4(0, 0, 0, 0), r1 = make_float4(0, 0, 0, 0);
        #pragma unroll
        for (int c2 = 0; c2 < 4; c2++) {
            float4 p0 = *(const float4*)(src + c2 * 1024);
            float4 p1 = *(const float4*)(src + c2 * 1024 + 4);
            r0.x += p0.x; r0.y += p0.y; r0.z += p0.z; r0.w += p0.w;
            r1.x += p1.x; r1.y += p1.y; r1.z += p1.z; r1.w += p1.w;
        }
        *(float4*)&s_kv[e]     = r0;
        *(float4*)&s_kv[e + 4] = r1;
        if (tid < 64) {
            float s = 0.0f;
            #pragma unroll
            for (int c2 = 0; c2 < 4; c2++) s += ksp[(tid >> 5) * 128 + c2 * 32 + (tid & 31)];
            s_ks[tid] = s;
        }
    }
    __syncthreads();

    {
        const float* Pg0 = g_P + (size_t)t0 * 512 + 384 + h * 32;
        #pragma unroll
        for (int it = 0; it < 8; it++) {
            int idx = it * 256 + tid;
            int token = idx >> 3, c4 = idx & 7;
            cpasync16(R1u + (unsigned)(token * 36 + c4 * 4) * 4,
                      Pg0 + (size_t)token * 512 + c4 * 4);
        }
        CP_COMMIT();
    }

    u64 num2[16];
    #pragma unroll
    for (int q = 0; q < 16; q++) num2[q] = 0ull;
    float den = 0.0f;
    {
        const ulonglong2* qp = (const ulonglong2*)(s_q + tid * 36);
        u64 q2[16];
        #pragma unroll
        for (int i = 0; i < 8; i++) {
            ulonglong2 qq = qp[i];
            q2[2 * i] = qq.x; q2[2 * i + 1] = qq.y;
        }
        #pragma unroll 4
        for (int row = 0; row < 32; row++) {
            const u64* wr = (const u64*)&s_w[row * 32];
            u64 a2 = 0ull, b2 = 0ull;
            #pragma unroll
            for (int dp = 0; dp < 8; dp++) {
                ffma2(a2, wr[2 * dp],     q2[2 * dp]);
                ffma2(b2, wr[2 * dp + 1], q2[2 * dp + 1]);
            }
            float2 fa = funpk(a2), fb = funpk(b2);
            float m = (fa.x + fa.y) + (fb.x + fb.y) + s_w[1024 + row];
            m = fminf(8.0f, fmaxf(-8.0f, m));
            float e  = __expf(m);
            float ei = __expf(-m);
            den += e  * s_ks[row];
            den += ei * s_ks[row + 32];
            u64 e2 = frep2(e), ei2 = frep2(ei);
            const ulonglong2* k1 = (const ulonglong2*)&s_kv[row * 32];
            const ulonglong2* k2 = (const ulonglong2*)&s_kv[(row + 32) * 32];
            #pragma unroll
            for (int q = 0; q < 8; q++) {
                ulonglong2 ka = k1[q];
                ffma2(num2[2 * q],     e2, ka.x);
                ffma2(num2[2 * q + 1], e2, ka.y);
            }
            #pragma unroll
            for (int q = 0; q < 8; q++) {
                ulonglong2 kb = k2[q];
                ffma2(num2[2 * q],     ei2, kb.x);
                ffma2(num2[2 * q + 1], ei2, kb.y);
            }
        }
    }
    den = fmaxf(den, 1e-6f);
    float inv = 1.0f / den;
    CP_WAIT(0);
    __syncthreads();

    {
        float* grow = R1 + tid * 36;
        #pragma unroll
        for (int i = 0; i < 8; i++) {
            float2 ua = funpk(num2[2 * i]);
            float2 ub = funpk(num2[2 * i + 1]);
            float4 gv = *(float4*)(grow + 4 * i);
            float4 o;
            o.x = __fdividef(1.0f, 1.0f + __expf(-gv.x)) * ua.x * inv;
            o.y = __fdividef(1.0f, 1.0f + __expf(-gv.y)) * ua.y * inv;
            o.z = __fdividef(1.0f, 1.0f + __expf(-gv.z)) * ub.x * inv;
            o.w = __fdividef(1.0f, 1.0f + __expf(-gv.w)) * ub.y * inv;
            *(float4*)(grow + 4 * i) = o;
        }
    }
    __syncthreads();
    {
        float* GA0 = g_GA + (size_t)t0 * 128 + h * 32;
        #pragma unroll
        for (int it = 0; it < 8; it++) {
            int idx = it * 256 + tid;
            int token = idx >> 3, c4 = idx & 7;
            float4 o = *(const float4*)(R1 + token * 36 + c4 * 4);
            *(float4*)(GA0 + (size_t)token * 128 + c4 * 4) = o;
        }
    }
}

// ---------------- launcher ----------------
extern "C" void kernel_launch(void* const* d_in, const int* in_sizes, int n_in,
                              void* d_out, int out_size) {
    const float* z    = (const float*)d_in[0];
    const int*   pm   = (const int*)  d_in[1];
    const float* lnw  = (const float*)d_in[2];
    const float* lnb  = (const float*)d_in[3];
    const float* qw   = (const float*)d_in[4];
    const float* qb   = (const float*)d_in[5];
    const float* kw   = (const float*)d_in[6];
    const float* kb   = (const float*)d_in[7];
    const float* vw   = (const float*)d_in[8];
    const float* vb   = (const float*)d_in[9];
    const float* qfw  = (const float*)d_in[10];
    const float* qfb  = (const float*)d_in[11];
    const float* kfw  = (const float*)d_in[12];
    const float* kfb  = (const float*)d_in[13];
    const float* gw   = (const float*)d_in[14];
    const float* gb   = (const float*)d_in[15];
    const float* ow   = (const float*)d_in[16];
    const float* ob   = (const float*)d_in[17];
    float* out = (float*)d_out;

    static int attr_set = 0;
    if (!attr_set) {
        cudaFuncSetAttribute(attn_kernel, cudaFuncAttributeMaxDynamicSharedMemorySize, 114816);
        cudaFuncSetAttribute(gemm_proj,   cudaFuncAttributeMaxDynamicSharedMemorySize, 61440);
        cudaFuncSetAttribute(mma_gemm2,   cudaFuncAttributeMaxDynamicSharedMemorySize, 104448);
        attr_set = 1;
    }

    pack_kernel<<<320, 256>>>(qw, kw, vw, gw, qb, kb, vb, gb, ow);
    ln_kernel<<<8192, 256>>>(z, lnw, lnb);
    gemm_proj<<<dim3(1024, 4), 256, 61440>>>();
    attn_kernel<<<dim3(256, 4), 256, 114816>>>(pm, qfw, qfb, kfw, kfb);
    mma_gemm2<<<dim3(1024, 1), 256, 104448>>>(ob, pm, out);
}

// round 15
// speedup vs baseline: 1.1639x; 1.0628x over previous
#include <cuda_runtime.h>
#include <cuda_bf16.h>

// ---------------- scratch (static device memory; no allocation) ----------------
__device__ float         g_P [65536ull * 512];   // q|k|v|g projections (row-major)
__device__ float         g_GA[65536ull * 128];   // gate * attn_out (row-major)
__device__ __nv_bfloat16 g_znh[8388608];          // layernormed z hi [token][128]
__device__ __nv_bfloat16 g_znl[8388608];          // layernormed z lo
__device__ __nv_bfloat16 g_Wh[65536], g_Wl[65536];   // packed q|k|v|g weights [512][128]
__device__ __nv_bfloat16 g_Oh[16384], g_Ol[16384];   // o_w [128][128]
__device__ float         g_Bcat[512];                 // packed q|k|v|g biases

typedef unsigned long long u64;

// ---------------- f32x2 packed-FMA helpers ----------------
__device__ __forceinline__ u64 frep2(float x) {
    u64 r; asm("mov.b64 %0, {%1, %1};" : "=l"(r) : "f"(x)); return r;
}
__device__ __forceinline__ void ffma2(u64& d, u64 a, u64 b) {
    asm("fma.rn.f32x2 %0, %1, %2, %0;" : "+l"(d) : "l"(a), "l"(b));
}
__device__ __forceinline__ float2 funpk(u64 d) {
    float2 f; asm("mov.b64 {%0, %1}, %2;" : "=f"(f.x), "=f"(f.y) : "l"(d)); return f;
}

// ---------------- cp.async helpers ----------------
__device__ __forceinline__ void cpasync16(unsigned dst, const void* src) {
    asm volatile("cp.async.cg.shared.global [%0], [%1], 16;" :: "r"(dst), "l"(src));
}
#define CP_COMMIT() asm volatile("cp.async.commit_group;" ::: "memory")
#define CP_WAIT(n)  asm volatile("cp.async.wait_group %0;" :: "n"(n) : "memory")

// ---------------- tensor-core helpers ----------------
__device__ __forceinline__ unsigned smem_u32p(const void* p) {
    return (unsigned)__cvta_generic_to_shared(p);
}
__device__ __forceinline__ void ldmx4(unsigned* r, unsigned addr) {
    asm volatile("ldmatrix.sync.aligned.m8n8.x4.shared.b16 {%0,%1,%2,%3}, [%4];"
        : "=r"(r[0]), "=r"(r[1]), "=r"(r[2]), "=r"(r[3]) : "r"(addr));
}
__device__ __forceinline__ void ldmx2(unsigned* r, unsigned addr) {
    asm volatile("ldmatrix.sync.aligned.m8n8.x2.shared.b16 {%0,%1}, [%2];"
        : "=r"(r[0]), "=r"(r[1]) : "r"(addr));
}
__device__ __forceinline__ void mma16816(float* c, const unsigned* a, const unsigned* b) {
    asm volatile("mma.sync.aligned.m16n8k16.row.col.f32.bf16.bf16.f32 "
        "{%0,%1,%2,%3}, {%4,%5,%6,%7}, {%8,%9}, {%0,%1,%2,%3};"
        : "+f"(c[0]), "+f"(c[1]), "+f"(c[2]), "+f"(c[3])
        : "r"(a[0]), "r"(a[1]), "r"(a[2]), "r"(a[3]), "r"(b[0]), "r"(b[1]));
}
__device__ __forceinline__ void bf16split(float x, __nv_bfloat16& h, __nv_bfloat16& l) {
    h = __float2bfloat16_rn(x);
    l = __float2bfloat16_rn(x - __bfloat162float(h));
}

// ---------------- K0: pack + split weights ----------------
__global__ void pack_kernel(const float* __restrict__ qw, const float* __restrict__ kw,
                            const float* __restrict__ vw, const float* __restrict__ gw,
                            const float* __restrict__ qb, const float* __restrict__ kb,
                            const float* __restrict__ vb, const float* __restrict__ gb,
                            const float* __restrict__ ow) {
    int idx = blockIdx.x * 256 + threadIdx.x;   // 0 .. 81919
    if (idx < 65536) {
        int row = idx >> 7, col = idx & 127;
        const float* w = (row < 128) ? qw : (row < 256) ? kw : (row < 384) ? vw : gw;
        float x = w[(row & 127) * 128 + col];
        __nv_bfloat16 h, l; bf16split(x, h, l);
        g_Wh[idx] = h; g_Wl[idx] = l;
        if (idx < 512) {
            const float* b = (idx < 128) ? qb : (idx < 256) ? kb : (idx < 384) ? vb : gb;
            g_Bcat[idx] = b[idx & 127];
        }
    } else if (idx < 81920) {
        int i = idx - 65536;
        __nv_bfloat16 h, l; bf16split(ow[i], h, l);
        g_Oh[i] = h; g_Ol[i] = l;
    }
}

// ---------------- K1: LayerNorm -> bf16 hi/lo ----------------
__global__ void ln_kernel(const float* __restrict__ z,
                          const float* __restrict__ lw,
                          const float* __restrict__ lb) {
    int warp = threadIdx.x >> 5, lane = threadIdx.x & 31;
    int t = blockIdx.x * 8 + warp;
    const float4* zp = (const float4*)(z + (size_t)t * 128);
    float4 v = zp[lane];
    float s = v.x + v.y + v.z + v.w;
    float q = v.x * v.x + v.y * v.y + v.z * v.z + v.w * v.w;
    #pragma unroll
    for (int o = 16; o; o >>= 1) {
        s += __shfl_xor_sync(0xFFFFFFFFu, s, o);
        q += __shfl_xor_sync(0xFFFFFFFFu, q, o);
    }
    float mu  = s * (1.0f / 128.0f);
    float var = q * (1.0f / 128.0f) - mu * mu;
    float rs  = rsqrtf(var + 1e-5f);
    float4 w4 = ((const float4*)lw)[lane];
    float4 b4 = ((const float4*)lb)[lane];
    float o4[4];
    o4[0] = (v.x - mu) * rs * w4.x + b4.x;
    o4[1] = (v.y - mu) * rs * w4.y + b4.y;
    o4[2] = (v.z - mu) * rs * w4.z + b4.z;
    o4[3] = (v.w - mu) * rs * w4.w + b4.w;
    __nv_bfloat16 h[4], l[4];
    #pragma unroll
    for (int i = 0; i < 4; i++) bf16split(o4[i], h[i], l[i]);
    size_t base = (size_t)t * 128 + lane * 4;
    *(__nv_bfloat162*)(g_znh + base)     = __nv_bfloat162(h[0], h[1]);
    *(__nv_bfloat162*)(g_znh + base + 2) = __nv_bfloat162(h[2], h[3]);
    *(__nv_bfloat162*)(g_znl + base)     = __nv_bfloat162(l[0], l[1]);
    *(__nv_bfloat162*)(g_znl + base + 2) = __nv_bfloat162(l[2], l[3]);
}

// ---------------- K2: pipelined proj GEMM (round-14 verbatim) ----------------
__global__ void __launch_bounds__(256, 3) gemm_proj(void) {
    extern __shared__ __nv_bfloat16 smem[];
    const int BUF = 15360;
    int tid = threadIdx.x;
    int bm0 = blockIdx.x * 64;
    int bn0 = blockIdx.y * 128;

    int wid = tid >> 5, lane = tid & 31;
    int warp_m = (wid & 1) * 32, warp_n = (wid >> 1) * 32;
    int arow = warp_m + (lane & 15);
    int kofa = (lane >> 4) * 8;
    int brow = warp_n + (lane & 7);
    int kofb = ((lane >> 3) & 1) * 8;

    auto load_stage = [&](int ks, int buf) {
        unsigned baseu = smem_u32p(smem + buf * BUF);
        #pragma unroll
        for (int it = 0; it < 6; it++) {
            int t = it * 256 + tid;
            int i = t & 511;
            int row = i >> 2, ch = i & 3;
            if (t < 256) {
                cpasync16(baseu + (unsigned)(row * 40 + ch * 8) * 2,
                          g_znh + (size_t)(bm0 + row) * 128 + ks + ch * 8);
            } else if (t < 512) {
                cpasync16(baseu + (unsigned)(2560 + (row - 64) * 40 + ch * 8) * 2,
                          g_znl + (size_t)(bm0 + row - 64) * 128 + ks + ch * 8);
            } else if (t < 1024) {
                cpasync16(baseu + (unsigned)(5120 + row * 40 + ch * 8) * 2,
                          g_Wh + (size_t)(bn0 + row) * 128 + ks + ch * 8);
            } else {
                cpasync16(baseu + (unsigned)(10240 + row * 40 + ch * 8) * 2,
                          g_Wl + (size_t)(bn0 + row) * 128 + ks + ch * 8);
            }
        }
        CP_COMMIT();
    };

    load_stage(0, 0);

    float acc[2][4][4];
    #pragma unroll
    for (int mi = 0; mi < 2; mi++)
        #pragma unroll
        for (int ni = 0; ni < 4; ni++)
            #pragma unroll
            for (int c = 0; c < 4; c++) acc[mi][ni][c] = 0.0f;

    #pragma unroll
    for (int s = 0; s < 4; s++) {
        if (s < 3) { load_stage((s + 1) * 32, (s + 1) & 1); CP_WAIT(1); }
        else       { CP_WAIT(0); }
        __syncthreads();
        unsigned bAh = smem_u32p(smem + (s & 1) * BUF);
        unsigned bAl = bAh + 2560 * 2;
        unsigned bBh = bAh + 5120 * 2;
        unsigned bBl = bAh + 10240 * 2;
        #pragma unroll
        for (int kk = 0; kk < 2; kk++) {
            unsigned ah[2][4], al[2][4], bh[4][2], bl[4][2];
            #pragma unroll
            for (int mi = 0; mi < 2; mi++) {
                unsigned ao = (unsigned)((arow + mi * 16) * 80 + (kk * 16 + kofa) * 2);
                ldmx4(ah[mi], bAh + ao);
                ldmx4(al[mi], bAl + ao);
            }
            #pragma unroll
            for (int ni = 0; ni < 4; ni++) {
                unsigned bo = (unsigned)((brow + ni * 8) * 80 + (kk * 16 + kofb) * 2);
                ldmx2(bh[ni], bBh + bo);
                ldmx2(bl[ni], bBl + bo);
            }
            #pragma unroll
            for (int mi = 0; mi < 2; mi++)
                #pragma unroll
                for (int ni = 0; ni < 4; ni++) {
                    mma16816(acc[mi][ni], ah[mi], bh[ni]);
                    mma16816(acc[mi][ni], ah[mi], bl[ni]);
                    mma16816(acc[mi][ni], al[mi], bh[ni]);
                }
        }
        __syncthreads();
    }

    #pragma unroll
    for (int mi = 0; mi < 2; mi++)
        #pragma unroll
        for (int ni = 0; ni < 4; ni++) {
            int row = bm0 + warp_m + mi * 16 + (lane >> 2);
            int col = bn0 + warp_n + ni * 8 + (lane & 3) * 2;
            float b0 = g_Bcat[col], b1 = g_Bcat[col + 1];
            *(float2*)&g_P[(size_t)row * 512 + col] =
                make_float2(acc[mi][ni][0] + b0, acc[mi][ni][1] + b1);
            *(float2*)&g_P[(size_t)(row + 8) * 512 + col] =
                make_float2(acc[mi][ni][2] + b0, acc[mi][ni][3] + b1);
        }
}

// ---------------- K4: output GEMM (round-14 verbatim) ----------------
__global__ void __launch_bounds__(256, 2) mma_gemm2(const float* __restrict__ obias,
                                                    const int*   __restrict__ mask,
                                                    float* __restrict__ Cout) {
    extern __shared__ __nv_bfloat16 smem[];
    __nv_bfloat16* sAh = smem;             // 64*136
    __nv_bfloat16* sAl = smem + 8704;
    __nv_bfloat16* sBh = smem + 17408;     // 128*136
    __nv_bfloat16* sBl = smem + 34816;
    int tid = threadIdx.x;
    int bm0 = blockIdx.x * 64;

    {
        const float4* srcA = (const float4*)(g_GA + (size_t)bm0 * 128);
        #pragma unroll
        for (int it = 0; it < 8; it++) {
            int idx = it * 256 + tid;
            int row = idx >> 5, c4 = idx & 31;
            float4 v = srcA[idx];
            int col = c4 * 4;
            __nv_bfloat16 h, l;
            bf16split(v.x, h, l); sAh[row * 136 + col]     = h; sAl[row * 136 + col]     = l;
            bf16split(v.y, h, l); sAh[row * 136 + col + 1] = h; sAl[row * 136 + col + 1] = l;
            bf16split(v.z, h, l); sAh[row * 136 + col + 2] = h; sAl[row * 136 + col + 2] = l;
            bf16split(v.w, h, l); sAh[row * 136 + col + 3] = h; sAl[row * 136 + col + 3] = l;
        }
    }
    {
        const uint4* srcH = (const uint4*)(g_Oh);
        const uint4* srcL = (const uint4*)(g_Ol);
        uint4* dBh = (uint4*)sBh; uint4* dBl = (uint4*)sBl;
        #pragma unroll
        for (int it = 0; it < 8; it++) {
            int idx = it * 256 + tid;
            int row = idx >> 4, ch = idx & 15;
            dBh[row * 17 + ch] = srcH[idx];
            dBl[row * 17 + ch] = srcL[idx];
        }
    }
    __syncthreads();

    int wid = tid >> 5, lane = tid & 31;
    int warp_m = (wid & 1) * 32, warp_n = (wid >> 1) * 32;
    unsigned baseAh = smem_u32p(sAh), baseAl = smem_u32p(sAl);
    unsigned baseBh = smem_u32p(sBh), baseBl = smem_u32p(sBl);
    int arow = warp_m + (lane & 15);
    int kofa = (lane >> 4) * 8;
    int brow = warp_n + (lane & 7);
    int kofb = ((lane >> 3) & 1) * 8;

    float acc[2][4][4];
    #pragma unroll
    for (int mi = 0; mi < 2; mi++)
        #pragma unroll
        for (int ni = 0; ni < 4; ni++)
            #pragma unroll
            for (int c = 0; c < 4; c++) acc[mi][ni][c] = 0.0f;

    #pragma unroll
    for (int ks = 0; ks < 8; ks++) {
        unsigned ah[2][4], al[2][4], bh[4][2], bl[4][2];
        #pragma unroll
        for (int mi = 0; mi < 2; mi++) {
            unsigned ao = (unsigned)((arow + mi * 16) * 272 + (ks * 16 + kofa) * 2);
            ldmx4(ah[mi], baseAh + ao);
            ldmx4(al[mi], baseAl + ao);
        }
        #pragma unroll
        for (int ni = 0; ni < 4; ni++) {
            unsigned bo = (unsigned)((brow + ni * 8) * 272 + (ks * 16 + kofb) * 2);
            ldmx2(bh[ni], baseBh + bo);
            ldmx2(bl[ni], baseBl + bo);
        }
        #pragma unroll
        for (int mi = 0; mi < 2; mi++)
            #pragma unroll
            for (int ni = 0; ni < 4; ni++) {
                mma16816(acc[mi][ni], ah[mi], bh[ni]);
                mma16816(acc[mi][ni], ah[mi], bl[ni]);
                mma16816(acc[mi][ni], al[mi], bh[ni]);
            }
    }

    #pragma unroll
    for (int mi = 0; mi < 2; mi++)
        #pragma unroll
        for (int ni = 0; ni < 4; ni++) {
            int row = bm0 + warp_m + mi * 16 + (lane >> 2);
            int col = warp_n + ni * 8 + (lane & 3) * 2;
            float b0 = obias[col], b1 = obias[col + 1];
            float m0 = (float)mask[row], m1 = (float)mask[row + 8];
            *(float2*)&Cout[(size_t)row * 128 + col] =
                make_float2((acc[mi][ni][0] + b0) * m0, (acc[mi][ni][1] + b1) * m0);
            *(float2*)&Cout[(size_t)(row + 8) * 128 + col] =
                make_float2((acc[mi][ni][2] + b0) * m1, (acc[mi][ni][3] + b1) * m1);
        }
}

// ---------------- K3: attn — steps A/B as round 14; step C tensor-ized ----------------
// smem (floats): R1 @0 [9216], R2a @9216 [4608], R2b @13824 [4608],
//                s_q @18432 [9216], s_w @27648 [1056]  -> 114816 B, 2 CTAs/SM
__global__ void __launch_bounds__(256, 2) attn_kernel(const int*   __restrict__ pm,
                                                      const float* __restrict__ qfw,
                                                      const float* __restrict__ qfb,
                                                      const float* __restrict__ kfw,
                                                      const float* __restrict__ kfb) {
    extern __shared__ float sm[];
    float* R1     = sm;             // 9216
    float* R2a    = sm + 9216;      // 4608
    float* R2b    = sm + 13824;     // 4608
    float* s_q    = sm + 18432;     // 9216
    float* s_w    = sm + 27648;     // 1056

    unsigned R1u  = smem_u32p(R1);
    unsigned R2au = smem_u32p(R2a);
    unsigned R2bu = smem_u32p(R2b);
    unsigned squ  = smem_u32p(s_q);

    int tid = threadIdx.x;
    int r = blockIdx.x, h = blockIdx.y;
    int t0 = r * 256;
    int lane = tid & 31, w = tid >> 5;

    // ---- prologue: k chunk0 + full q ----
    {
        const float* Pk0 = g_P + (size_t)t0 * 512 + 128 + h * 32;
        #pragma unroll
        for (int it = 0; it < 4; it++) {
            int idx = it * 256 + tid;
            int token = idx >> 3, c4 = idx & 7;
            cpasync16(R2au + (unsigned)(token * 36 + c4 * 4) * 4,
                      Pk0 + (size_t)token * 512 + c4 * 4);
        }
        CP_COMMIT();
        const float* Pq0 = g_P + (size_t)t0 * 512 + h * 32;
        #pragma unroll
        for (int it = 0; it < 8; it++) {
            int idx = it * 256 + tid;
            int token = idx >> 3, c4 = idx & 7;
            cpasync16(squ + (unsigned)(token * 36 + c4 * 4) * 4,
                      Pq0 + (size_t)token * 512 + c4 * 4);
        }
        CP_COMMIT();
    }

    for (int i = tid; i < 1024; i += 256) s_w[i] = kfw[i];
    if (tid < 32) s_w[1024 + tid] = kfb[tid];

    int fhalf = w & 1, tg = w >> 1;
    int fy = lane >> 2, dx = lane & 3;
    int fbase = fhalf * 32 + fy * 4;
    u64 acc2[4][4];
    float ks[4];
    #pragma unroll
    for (int j = 0; j < 4; j++) {
        ks[j] = 0.0f;
        #pragma unroll
        for (int q = 0; q < 4; q++) acc2[j][q] = 0ull;
    }

    #pragma unroll 1
    for (int c = 0; c < 2; c++) {
        if (c == 0) { CP_WAIT(1); } else { CP_WAIT(0); }
        __syncthreads();
        {
            const float* Pv = g_P + (size_t)(t0 + c * 128) * 512 + 256 + h * 32;
            #pragma unroll
            for (int it = 0; it < 4; it++) {
                int idx = it * 256 + tid;
                int token = idx >> 3, c4 = idx & 7;
                cpasync16(R2bu + (unsigned)(token * 36 + c4 * 4) * 4,
                          Pv + (size_t)token * 512 + c4 * 4);
            }
            CP_COMMIT();
        }
        {
            int tk = tid & 127, hh = tid >> 7;
            float mk = (float)pm[t0 + c * 128 + tk];
            const ulonglong2* kp = (const ulonglong2*)(R2a + tk * 36);
            u64 k2[16];
            #pragma unroll
            for (int i = 0; i < 8; i++) {
                ulonglong2 kk = kp[i];
                k2[2 * i] = kk.x; k2[2 * i + 1] = kk.y;
            }
            #pragma unroll
            for (int rr = 0; rr < 16; rr++) {
                int row = hh * 16 + rr;
                const u64* wr = (const u64*)&s_w[row * 32];
                u64 a2 = 0ull, b2 = 0ull;
                #pragma unroll
                for (int dp = 0; dp < 8; dp++) {
                    ffma2(a2, wr[2 * dp],     k2[2 * dp]);
                    ffma2(b2, wr[2 * dp + 1], k2[2 * dp + 1]);
                }
                float2 fa = funpk(a2), fb = funpk(b2);
                float m = (fa.x + fa.y) + (fb.x + fb.y) + s_w[1024 + row];
                m = fminf(8.0f, fmaxf(-8.0f, m));
                R1[tk * 66 + row]      = __expf(m)  * mk;
                R1[tk * 66 + 32 + row] = __expf(-m) * mk;
            }
        }
        __syncthreads();
        if (c == 0) {
            const float* Pk1 = g_P + (size_t)(t0 + 128) * 512 + 128 + h * 32;
            #pragma unroll
            for (int it = 0; it < 4; it++) {
                int idx = it * 256 + tid;
                int token = idx >> 3, c4 = idx & 7;
                cpasync16(R2au + (unsigned)(token * 36 + c4 * 4) * 4,
                          Pk1 + (size_t)token * 512 + c4 * 4);
            }
            CP_COMMIT();
            CP_WAIT(1);
        } else {
            CP_WAIT(0);
        }
        __syncthreads();
        #pragma unroll 2
        for (int i = 0; i < 32; i++) {
            int nn = tg * 32 + i;
            float2 kfa  = *(const float2*)&R1[nn * 66 + fbase];
            float2 kfb2 = *(const float2*)&R1[nn * 66 + fbase + 2];
            u64 kf2[4];
            kf2[0] = frep2(kfa.x);  kf2[1] = frep2(kfa.y);
            kf2[2] = frep2(kfb2.x); kf2[3] = frep2(kfb2.y);
            const ulonglong2* vmp = (const ulonglong2*)(R2b + nn * 36 + dx * 8);
            ulonglong2 v0 = vmp[0], v1 = vmp[1];
            u64 vm2[4] = {v0.x, v0.y, v1.x, v1.y};
            #pragma unroll
            for (int j = 0; j < 4; j++)
                #pragma unroll
                for (int q = 0; q < 4; q++) ffma2(acc2[j][q], kf2[j], vm2[q]);
            if (dx == 0) {
                ks[0] += kfa.x; ks[1] += kfa.y; ks[2] += kfb2.x; ks[3] += kfb2.y;
            }
        }
        __syncthreads();
    }

    // ---- spill partials + reload qf weights ----
    float* kvp = R1;
    float* ksp = R1 + 8192;
    #pragma unroll
    for (int j = 0; j < 4; j++) {
        float2 u0 = funpk(acc2[j][0]), u1 = funpk(acc2[j][1]);
        float2 u2 = funpk(acc2[j][2]), u3 = funpk(acc2[j][3]);
        float* dst = &kvp[fhalf * 4096 + tg * 1024 + (fy * 4 + j) * 32 + dx * 8];
        *(float4*)dst       = make_float4(u0.x, u0.y, u1.x, u1.y);
        *(float4*)(dst + 4) = make_float4(u2.x, u2.y, u3.x, u3.y);
    }
    if (dx == 0) {
        #pragma unroll
        for (int j = 0; j < 4; j++) ksp[fhalf * 128 + tg * 32 + fy * 4 + j] = ks[j];
    }
    for (int i = tid; i < 1024; i += 256) s_w[i] = qfw[i];
    if (tid < 32) s_w[1024 + tid] = qfb[tid];
    __syncthreads();

    // ---- reduce 4 copies -> s_kv[2048] + s_ks[64] in R2a ----
    float* s_kv = R2a;
    float* s_ks = R2a + 2048;
    {
        int e = tid * 8;
        int f = e >> 5, d0 = e & 31;
        const float* src = &kvp[(f >> 5) * 4096 + (f & 31) * 32 + d0];
        float4 r0 = make_float4(0, 0, 0, 0), r1 = make_float4(0, 0, 0, 0);
        #pragma unroll
        for (int c2 = 0; c2 < 4; c2++) {
            float4 p0 = *(const float4*)(src + c2 * 1024);
            float4 p1 = *(const float4*)(src + c2 * 1024 + 4);
            r0.x += p0.x; r0.y += p0.y; r0.z += p0.z; r0.w += p0.w;
            r1.x += p1.x; r1.y += p1.y; r1.z += p1.z; r1.w += p1.w;
        }
        *(float4*)&s_kv[e]     = r0;
        *(float4*)&s_kv[e + 4] = r1;
        if (tid < 64) {
            float s = 0.0f;
            #pragma unroll
            for (int c2 = 0; c2 < 4; c2++) s += ksp[(tid >> 5) * 128 + c2 * 32 + (tid & 31)];
            s_ks[tid] = s;
        }
    }
    __syncthreads();

    // ---- issue g (pass 0, tokens 0..127) into R1[0 .. 4608 floats) ----
    {
        const float* Pg0 = g_P + (size_t)t0 * 512 + 384 + h * 32;
        #pragma unroll
        for (int it = 0; it < 4; it++) {
            int idx = it * 256 + tid;          // 0..1023 -> token 0..127
            int token = idx >> 3, c4 = idx & 7;
            cpasync16(R1u + (unsigned)(token * 36 + c4 * 4) * 4,
                      Pg0 + (size_t)token * 512 + c4 * 4);
        }
        CP_COMMIT();
    }

    // ---- convert kv/ks -> transposed bf16-split KVT[40][72] in R2b ----
    __nv_bfloat16* KVTh = (__nv_bfloat16*)R2b;           // 40*72 = 2880 elems
    __nv_bfloat16* KVTl = KVTh + 2880;
    {
        int e = tid * 8;
        int f = e >> 5, d0 = e & 31;
        const float* src = &s_kv[f * 32 + d0];
        #pragma unroll
        for (int j = 0; j < 8; j++) {
            __nv_bfloat16 hh2, ll2; bf16split(src[j], hh2, ll2);
            KVTh[(d0 + j) * 72 + f] = hh2;
            KVTl[(d0 + j) * 72 + f] = ll2;
        }
        if (tid < 64) {
            __nv_bfloat16 hh2, ll2; bf16split(s_ks[tid], hh2, ll2);
            KVTh[32 * 72 + tid] = hh2;
            KVTl[32 * 72 + tid] = ll2;
        }
        // zero rows 33..39 (junk safety)
        for (int i = tid; i < 504; i += 256) {
            KVTh[2376 + i] = __float2bfloat16_rn(0.0f);
            KVTl[2376 + i] = __float2bfloat16_rn(0.0f);
        }
    }
    __syncthreads();

    // ---- step C: two M=128 passes, QF bf16-split, mma ----
    __nv_bfloat16* QFh = (__nv_bfloat16*)R2a;            // [128][72]
    __nv_bfloat16* QFl = (__nv_bfloat16*)(R1 + 4608);    // [128][72]
    unsigned QFhu = smem_u32p(QFh), QFlu = smem_u32p(QFl);
    unsigned KVThu = smem_u32p(KVTh), KVTlu = smem_u32p(KVTl);
    int warp_m = w * 16;
    int arow = warp_m + (lane & 15);
    int kofa = (lane >> 4) * 8;
    int brow8 = lane & 7;
    int kofb = ((lane >> 3) & 1) * 8;

    #pragma unroll 1
    for (int p = 0; p < 2; p++) {
        // features -> QF (2 threads per token, 16 rows each)
        {
            int tk = tid & 127, hh = tid >> 7;
            const ulonglong2* qp = (const ulonglong2*)(s_q + (p * 128 + tk) * 36);
            u64 q2[16];
            #pragma unroll
            for (int i = 0; i < 8; i++) {
                ulonglong2 qq = qp[i];
                q2[2 * i] = qq.x; q2[2 * i + 1] = qq.y;
            }
            #pragma unroll
            for (int rr = 0; rr < 16; rr++) {
                int row = hh * 16 + rr;
                const u64* wr = (const u64*)&s_w[row * 32];
                u64 a2 = 0ull, b2 = 0ull;
                #pragma unroll
                for (int dp = 0; dp < 8; dp++) {
                    ffma2(a2, wr[2 * dp],     q2[2 * dp]);
                    ffma2(b2, wr[2 * dp + 1], q2[2 * dp + 1]);
                }
                float2 fa = funpk(a2), fb = funpk(b2);
                float m = (fa.x + fa.y) + (fb.x + fb.y) + s_w[1024 + row];
                m = fminf(8.0f, fmaxf(-8.0f, m));
                float e  = __expf(m);
                float ei = __expf(-m);
                __nv_bfloat16 eh, el; bf16split(e, eh, el);
                QFh[tk * 72 + row] = eh; QFl[tk * 72 + row] = el;
                bf16split(ei, eh, el);
                QFh[tk * 72 + row + 32] = eh; QFl[tk * 72 + row + 32] = el;
            }
        }
        __syncthreads();

        // mma: M=128 (16/warp), N=40, K=64
        float acc[5][4];
        #pragma unroll
        for (int ni = 0; ni < 5; ni++)
            #pragma unroll
            for (int c2 = 0; c2 < 4; c2++) acc[ni][c2] = 0.0f;
        #pragma unroll
        for (int ks2 = 0; ks2 < 4; ks2++) {
            unsigned ah[4], al[4];
            unsigned ao = (unsigned)(arow * 144 + (ks2 * 16 + kofa) * 2);
            ldmx4(ah, QFhu + ao);
            ldmx4(al, QFlu + ao);
            #pragma unroll
            for (int ni = 0; ni < 5; ni++) {
                unsigned bo = (unsigned)((ni * 8 + brow8) * 144 + (ks2 * 16 + kofb) * 2);
                unsigned bh2[2], bl2[2];
                ldmx2(bh2, KVThu + bo);
                ldmx2(bl2, KVTlu + bo);
                mma16816(acc[ni], ah, bh2);
                mma16816(acc[ni], ah, bl2);
                mma16816(acc[ni], al, bh2);
            }
        }
        CP_WAIT(0);        // g for this pass landed
        __syncthreads();

        // den broadcast + gated epilogue
        {
            int srcl = lane & ~3;
            float den0 = __shfl_sync(0xFFFFFFFFu, acc[4][0], srcl);
            float den1 = __shfl_sync(0xFFFFFFFFu, acc[4][2], srcl);
            float inv0 = 1.0f / fmaxf(den0, 1e-6f);
            float inv1 = 1.0f / fmaxf(den1, 1e-6f);
            int row0 = warp_m + (lane >> 2);
            int row1 = row0 + 8;
            float* GAbase = g_GA + (size_t)(t0 + p * 128) * 128 + h * 32;
            #pragma unroll
            for (int ni = 0; ni < 4; ni++) {
                int col = ni * 8 + (lane & 3) * 2;
                float2 g0 = *(const float2*)&R1[row0 * 36 + col];
                float2 g1 = *(const float2*)&R1[row1 * 36 + col];
                float2 o0, o1;
                o0.x = __fdividef(1.0f, 1.0f + __expf(-g0.x)) * acc[ni][0] * inv0;
                o0.y = __fdividef(1.0f, 1.0f + __expf(-g0.y)) * acc[ni][1] * inv0;
                o1.x = __fdividef(1.0f, 1.0f + __expf(-g1.x)) * acc[ni][2] * inv1;
                o1.y = __fdividef(1.0f, 1.0f + __expf(-g1.y)) * acc[ni][3] * inv1;
                *(float2*)(GAbase + (size_t)row0 * 128 + col) = o0;
                *(float2*)(GAbase + (size_t)row1 * 128 + col) = o1;
            }
        }
        __syncthreads();
        if (p == 0) {
            const float* Pg1 = g_P + (size_t)(t0 + 128) * 512 + 384 + h * 32;
            #pragma unroll
            for (int it = 0; it < 4; it++) {
                int idx = it * 256 + tid;
                int token = idx >> 3, c4 = idx & 7;
                cpasync16(R1u + (unsigned)(token * 36 + c4 * 4) * 4,
                          Pg1 + (size_t)token * 512 + c4 * 4);
            }
            CP_COMMIT();
        }
    }
}

// ---------------- launcher ----------------
extern "C" void kernel_launch(void* const* d_in, const int* in_sizes, int n_in,
                              void* d_out, int out_size) {
    const float* z    = (const float*)d_in[0];
    const int*   pm   = (const int*)  d_in[1];
    const float* lnw  = (const float*)d_in[2];
    const float* lnb  = (const float*)d_in[3];
    const float* qw   = (const float*)d_in[4];
    const float* qb   = (const float*)d_in[5];
    const float* kw   = (const float*)d_in[6];
    const float* kb   = (const float*)d_in[7];
    const float* vw   = (const float*)d_in[8];
    const float* vb   = (const float*)d_in[9];
    const float* qfw  = (const float*)d_in[10];
    const float* qfb  = (const float*)d_in[11];
    const float* kfw  = (const float*)d_in[12];
    const float* kfb  = (const float*)d_in[13];
    const float* gw   = (const float*)d_in[14];
    const float* gb   = (const float*)d_in[15];
    const float* ow   = (const float*)d_in[16];
    const float* ob   = (const float*)d_in[17];
    float* out = (float*)d_out;

    static int attr_set = 0;
    if (!attr_set) {
        cudaFuncSetAttribute(attn_kernel, cudaFuncAttributeMaxDynamicSharedMemorySize, 114816);
        cudaFuncSetAttribute(gemm_proj,   cudaFuncAttributeMaxDynamicSharedMemorySize, 61440);
        cudaFuncSetAttribute(mma_gemm2,   cudaFuncAttributeMaxDynamicSharedMemorySize, 104448);
        attr_set = 1;
    }

    pack_kernel<<<320, 256>>>(qw, kw, vw, gw, qb, kb, vb, gb, ow);
    ln_kernel<<<8192, 256>>>(z, lnw, lnb);
    gemm_proj<<<dim3(1024, 4), 256, 61440>>>();
    attn_kernel<<<dim3(256, 4), 256, 114816>>>(pm, qfw, qfb, kfw, kfb);
    mma_gemm2<<<dim3(1024, 1), 256, 104448>>>(ob, pm, out);
}

// round 16
// speedup vs baseline: 1.1666x; 1.0023x over previous
#include <cuda_runtime.h>
#include <cuda_bf16.h>

// ---------------- scratch (static device memory; no allocation) ----------------
__device__ float         g_P [65536ull * 512];   // q|k|v|g projections (row-major)
__device__ float         g_GA[65536ull * 128];   // gate * attn_out (row-major)
__device__ __nv_bfloat16 g_znh[8388608];          // layernormed z hi [token][128]
__device__ __nv_bfloat16 g_znl[8388608];          // layernormed z lo
__device__ __nv_bfloat16 g_Wh[65536], g_Wl[65536];   // packed q|k|v|g weights [512][128]
__device__ __nv_bfloat16 g_Oh[16384], g_Ol[16384];   // o_w [128][128]
__device__ float         g_Bcat[512];                 // packed q|k|v|g biases

typedef unsigned long long u64;

// ---------------- f32x2 packed-FMA helpers ----------------
__device__ __forceinline__ u64 frep2(float x) {
    u64 r; asm("mov.b64 %0, {%1, %1};" : "=l"(r) : "f"(x)); return r;
}
__device__ __forceinline__ void ffma2(u64& d, u64 a, u64 b) {
    asm("fma.rn.f32x2 %0, %1, %2, %0;" : "+l"(d) : "l"(a), "l"(b));
}
__device__ __forceinline__ float2 funpk(u64 d) {
    float2 f; asm("mov.b64 {%0, %1}, %2;" : "=f"(f.x), "=f"(f.y) : "l"(d)); return f;
}

// ---------------- cp.async helpers ----------------
__device__ __forceinline__ void cpasync16(unsigned dst, const void* src) {
    asm volatile("cp.async.cg.shared.global [%0], [%1], 16;" :: "r"(dst), "l"(src));
}
#define CP_COMMIT() asm volatile("cp.async.commit_group;" ::: "memory")
#define CP_WAIT(n)  asm volatile("cp.async.wait_group %0;" :: "n"(n) : "memory")

// ---------------- tensor-core helpers ----------------
__device__ __forceinline__ unsigned smem_u32p(const void* p) {
    return (unsigned)__cvta_generic_to_shared(p);
}
__device__ __forceinline__ void ldmx4(unsigned* r, unsigned addr) {
    asm volatile("ldmatrix.sync.aligned.m8n8.x4.shared.b16 {%0,%1,%2,%3}, [%4];"
        : "=r"(r[0]), "=r"(r[1]), "=r"(r[2]), "=r"(r[3]) : "r"(addr));
}
__device__ __forceinline__ void ldmx2(unsigned* r, unsigned addr) {
    asm volatile("ldmatrix.sync.aligned.m8n8.x2.shared.b16 {%0,%1}, [%2];"
        : "=r"(r[0]), "=r"(r[1]) : "r"(addr));
}
__device__ __forceinline__ void ldmx4t(unsigned* r, unsigned addr) {
    asm volatile("ldmatrix.sync.aligned.m8n8.x4.trans.shared.b16 {%0,%1,%2,%3}, [%4];"
        : "=r"(r[0]), "=r"(r[1]), "=r"(r[2]), "=r"(r[3]) : "r"(addr));
}
__device__ __forceinline__ void ldmx2t(unsigned* r, unsigned addr) {
    asm volatile("ldmatrix.sync.aligned.m8n8.x2.trans.shared.b16 {%0,%1}, [%2];"
        : "=r"(r[0]), "=r"(r[1]) : "r"(addr));
}
__device__ __forceinline__ void mma16816(float* c, const unsigned* a, const unsigned* b) {
    asm volatile("mma.sync.aligned.m16n8k16.row.col.f32.bf16.bf16.f32 "
        "{%0,%1,%2,%3}, {%4,%5,%6,%7}, {%8,%9}, {%0,%1,%2,%3};"
        : "+f"(c[0]), "+f"(c[1]), "+f"(c[2]), "+f"(c[3])
        : "r"(a[0]), "r"(a[1]), "r"(a[2]), "r"(a[3]), "r"(b[0]), "r"(b[1]));
}
__device__ __forceinline__ void bf16split(float x, __nv_bfloat16& h, __nv_bfloat16& l) {
    h = __float2bfloat16_rn(x);
    l = __float2bfloat16_rn(x - __bfloat162float(h));
}

// ---------------- K0: pack + split weights ----------------
__global__ void pack_kernel(const float* __restrict__ qw, const float* __restrict__ kw,
                            const float* __restrict__ vw, const float* __restrict__ gw,
                            const float* __restrict__ qb, const float* __restrict__ kb,
                            const float* __restrict__ vb, const float* __restrict__ gb,
                            const float* __restrict__ ow) {
    int idx = blockIdx.x * 256 + threadIdx.x;   // 0 .. 81919
    if (idx < 65536) {
        int row = idx >> 7, col = idx & 127;
        const float* w = (row < 128) ? qw : (row < 256) ? kw : (row < 384) ? vw : gw;
        float x = w[(row & 127) * 128 + col];
        __nv_bfloat16 h, l; bf16split(x, h, l);
        g_Wh[idx] = h; g_Wl[idx] = l;
        if (idx < 512) {
            const float* b = (idx < 128) ? qb : (idx < 256) ? kb : (idx < 384) ? vb : gb;
            g_Bcat[idx] = b[idx & 127];
        }
    } else if (idx < 81920) {
        int i = idx - 65536;
        __nv_bfloat16 h, l; bf16split(ow[i], h, l);
        g_Oh[i] = h; g_Ol[i] = l;
    }
}

// ---------------- K1: LayerNorm -> bf16 hi/lo ----------------
__global__ void ln_kernel(const float* __restrict__ z,
                          const float* __restrict__ lw,
                          const float* __restrict__ lb) {
    int warp = threadIdx.x >> 5, lane = threadIdx.x & 31;
    int t = blockIdx.x * 8 + warp;
    const float4* zp = (const float4*)(z + (size_t)t * 128);
    float4 v = zp[lane];
    float s = v.x + v.y + v.z + v.w;
    float q = v.x * v.x + v.y * v.y + v.z * v.z + v.w * v.w;
    #pragma unroll
    for (int o = 16; o; o >>= 1) {
        s += __shfl_xor_sync(0xFFFFFFFFu, s, o);
        q += __shfl_xor_sync(0xFFFFFFFFu, q, o);
    }
    float mu  = s * (1.0f / 128.0f);
    float var = q * (1.0f / 128.0f) - mu * mu;
    float rs  = rsqrtf(var + 1e-5f);
    float4 w4 = ((const float4*)lw)[lane];
    float4 b4 = ((const float4*)lb)[lane];
    float o4[4];
    o4[0] = (v.x - mu) * rs * w4.x + b4.x;
    o4[1] = (v.y - mu) * rs * w4.y + b4.y;
    o4[2] = (v.z - mu) * rs * w4.z + b4.z;
    o4[3] = (v.w - mu) * rs * w4.w + b4.w;
    __nv_bfloat16 h[4], l[4];
    #pragma unroll
    for (int i = 0; i < 4; i++) bf16split(o4[i], h[i], l[i]);
    size_t base = (size_t)t * 128 + lane * 4;
    *(__nv_bfloat162*)(g_znh + base)     = __nv_bfloat162(h[0], h[1]);
    *(__nv_bfloat162*)(g_znh + base + 2) = __nv_bfloat162(h[2], h[3]);
    *(__nv_bfloat162*)(g_znl + base)     = __nv_bfloat162(l[0], l[1]);
    *(__nv_bfloat162*)(g_znl + base + 2) = __nv_bfloat162(l[2], l[3]);
}

// ---------------- K2: pipelined proj GEMM (round-15 verbatim) ----------------
__global__ void __launch_bounds__(256, 3) gemm_proj(void) {
    extern __shared__ __nv_bfloat16 smem[];
    const int BUF = 15360;
    int tid = threadIdx.x;
    int bm0 = blockIdx.x * 64;
    int bn0 = blockIdx.y * 128;

    int wid = tid >> 5, lane = tid & 31;
    int warp_m = (wid & 1) * 32, warp_n = (wid >> 1) * 32;
    int arow = warp_m + (lane & 15);
    int kofa = (lane >> 4) * 8;
    int brow = warp_n + (lane & 7);
    int kofb = ((lane >> 3) & 1) * 8;

    auto load_stage = [&](int ks, int buf) {
        unsigned baseu = smem_u32p(smem + buf * BUF);
        #pragma unroll
        for (int it = 0; it < 6; it++) {
            int t = it * 256 + tid;
            int i = t & 511;
            int row = i >> 2, ch = i & 3;
            if (t < 256) {
                cpasync16(baseu + (unsigned)(row * 40 + ch * 8) * 2,
                          g_znh + (size_t)(bm0 + row) * 128 + ks + ch * 8);
            } else if (t < 512) {
                cpasync16(baseu + (unsigned)(2560 + (row - 64) * 40 + ch * 8) * 2,
                          g_znl + (size_t)(bm0 + row - 64) * 128 + ks + ch * 8);
            } else if (t < 1024) {
                cpasync16(baseu + (unsigned)(5120 + row * 40 + ch * 8) * 2,
                          g_Wh + (size_t)(bn0 + row) * 128 + ks + ch * 8);
            } else {
                cpasync16(baseu + (unsigned)(10240 + row * 40 + ch * 8) * 2,
                          g_Wl + (size_t)(bn0 + row) * 128 + ks + ch * 8);
            }
        }
        CP_COMMIT();
    };

    load_stage(0, 0);

    float acc[2][4][4];
    #pragma unroll
    for (int mi = 0; mi < 2; mi++)
        #pragma unroll
        for (int ni = 0; ni < 4; ni++)
            #pragma unroll
            for (int c = 0; c < 4; c++) acc[mi][ni][c] = 0.0f;

    #pragma unroll
    for (int s = 0; s < 4; s++) {
        if (s < 3) { load_stage((s + 1) * 32, (s + 1) & 1); CP_WAIT(1); }
        else       { CP_WAIT(0); }
        __syncthreads();
        unsigned bAh = smem_u32p(smem + (s & 1) * BUF);
        unsigned bAl = bAh + 2560 * 2;
        unsigned bBh = bAh + 5120 * 2;
        unsigned bBl = bAh + 10240 * 2;
        #pragma unroll
        for (int kk = 0; kk < 2; kk++) {
            unsigned ah[2][4], al[2][4], bh[4][2], bl[4][2];
            #pragma unroll
            for (int mi = 0; mi < 2; mi++) {
                unsigned ao = (unsigned)((arow + mi * 16) * 80 + (kk * 16 + kofa) * 2);
                ldmx4(ah[mi], bAh + ao);
                ldmx4(al[mi], bAl + ao);
            }
            #pragma unroll
            for (int ni = 0; ni < 4; ni++) {
                unsigned bo = (unsigned)((brow + ni * 8) * 80 + (kk * 16 + kofb) * 2);
                ldmx2(bh[ni], bBh + bo);
                ldmx2(bl[ni], bBl + bo);
            }
            #pragma unroll
            for (int mi = 0; mi < 2; mi++)
                #pragma unroll
                for (int ni = 0; ni < 4; ni++) {
                    mma16816(acc[mi][ni], ah[mi], bh[ni]);
                    mma16816(acc[mi][ni], ah[mi], bl[ni]);
                    mma16816(acc[mi][ni], al[mi], bh[ni]);
                }
        }
        __syncthreads();
    }

    #pragma unroll
    for (int mi = 0; mi < 2; mi++)
        #pragma unroll
        for (int ni = 0; ni < 4; ni++) {
            int row = bm0 + warp_m + mi * 16 + (lane >> 2);
            int col = bn0 + warp_n + ni * 8 + (lane & 3) * 2;
            float b0 = g_Bcat[col], b1 = g_Bcat[col + 1];
            *(float2*)&g_P[(size_t)row * 512 + col] =
                make_float2(acc[mi][ni][0] + b0, acc[mi][ni][1] + b1);
            *(float2*)&g_P[(size_t)(row + 8) * 512 + col] =
                make_float2(acc[mi][ni][2] + b0, acc[mi][ni][3] + b1);
        }
}

// ---------------- K4: output GEMM (round-15 verbatim) ----------------
__global__ void __launch_bounds__(256, 2) mma_gemm2(const float* __restrict__ obias,
                                                    const int*   __restrict__ mask,
                                                    float* __restrict__ Cout) {
    extern __shared__ __nv_bfloat16 smem[];
    __nv_bfloat16* sAh = smem;             // 64*136
    __nv_bfloat16* sAl = smem + 8704;
    __nv_bfloat16* sBh = smem + 17408;     // 128*136
    __nv_bfloat16* sBl = smem + 34816;
    int tid = threadIdx.x;
    int bm0 = blockIdx.x * 64;

    {
        const float4* srcA = (const float4*)(g_GA + (size_t)bm0 * 128);
        #pragma unroll
        for (int it = 0; it < 8; it++) {
            int idx = it * 256 + tid;
            int row = idx >> 5, c4 = idx & 31;
            float4 v = srcA[idx];
            int col = c4 * 4;
            __nv_bfloat16 h, l;
            bf16split(v.x, h, l); sAh[row * 136 + col]     = h; sAl[row * 136 + col]     = l;
            bf16split(v.y, h, l); sAh[row * 136 + col + 1] = h; sAl[row * 136 + col + 1] = l;
            bf16split(v.z, h, l); sAh[row * 136 + col + 2] = h; sAl[row * 136 + col + 2] = l;
            bf16split(v.w, h, l); sAh[row * 136 + col + 3] = h; sAl[row * 136 + col + 3] = l;
        }
    }
    {
        const uint4* srcH = (const uint4*)(g_Oh);
        const uint4* srcL = (const uint4*)(g_Ol);
        uint4* dBh = (uint4*)sBh; uint4* dBl = (uint4*)sBl;
        #pragma unroll
        for (int it = 0; it < 8; it++) {
            int idx = it * 256 + tid;
            int row = idx >> 4, ch = idx & 15;
            dBh[row * 17 + ch] = srcH[idx];
            dBl[row * 17 + ch] = srcL[idx];
        }
    }
    __syncthreads();

    int wid = tid >> 5, lane = tid & 31;
    int warp_m = (wid & 1) * 32, warp_n = (wid >> 1) * 32;
    unsigned baseAh = smem_u32p(sAh), baseAl = smem_u32p(sAl);
    unsigned baseBh = smem_u32p(sBh), baseBl = smem_u32p(sBl);
    int arow = warp_m + (lane & 15);
    int kofa = (lane >> 4) * 8;
    int brow = warp_n + (lane & 7);
    int kofb = ((lane >> 3) & 1) * 8;

    float acc[2][4][4];
    #pragma unroll
    for (int mi = 0; mi < 2; mi++)
        #pragma unroll
        for (int ni = 0; ni < 4; ni++)
            #pragma unroll
            for (int c = 0; c < 4; c++) acc[mi][ni][c] = 0.0f;

    #pragma unroll
    for (int ks = 0; ks < 8; ks++) {
        unsigned ah[2][4], al[2][4], bh[4][2], bl[4][2];
        #pragma unroll
        for (int mi = 0; mi < 2; mi++) {
            unsigned ao = (unsigned)((arow + mi * 16) * 272 + (ks * 16 + kofa) * 2);
            ldmx4(ah[mi], baseAh + ao);
            ldmx4(al[mi], baseAl + ao);
        }
        #pragma unroll
        for (int ni = 0; ni < 4; ni++) {
            unsigned bo = (unsigned)((brow + ni * 8) * 272 + (ks * 16 + kofb) * 2);
            ldmx2(bh[ni], baseBh + bo);
            ldmx2(bl[ni], baseBl + bo);
        }
        #pragma unroll
        for (int mi = 0; mi < 2; mi++)
            #pragma unroll
            for (int ni = 0; ni < 4; ni++) {
                mma16816(acc[mi][ni], ah[mi], bh[ni]);
                mma16816(acc[mi][ni], ah[mi], bl[ni]);
                mma16816(acc[mi][ni], al[mi], bh[ni]);
            }
    }

    #pragma unroll
    for (int mi = 0; mi < 2; mi++)
        #pragma unroll
        for (int ni = 0; ni < 4; ni++) {
            int row = bm0 + warp_m + mi * 16 + (lane >> 2);
            int col = warp_n + ni * 8 + (lane & 3) * 2;
            float b0 = obias[col], b1 = obias[col + 1];
            float m0 = (float)mask[row], m1 = (float)mask[row + 8];
            *(float2*)&Cout[(size_t)row * 128 + col] =
                make_float2((acc[mi][ni][0] + b0) * m0, (acc[mi][ni][1] + b1) * m0);
            *(float2*)&Cout[(size_t)(row + 8) * 128 + col] =
                make_float2((acc[mi][ni][2] + b0) * m1, (acc[mi][ni][3] + b1) * m1);
        }
}

// ---------------- K3: attn — steps B AND C tensor-ized ----------------
// smem 114816 B, 2 CTAs/SM. float-offset map:
//   region KF @0     [9216]: KFh/KFl bf16 [128][72];  phase C: KVTh/KVTl (2880 fl) + g[128][36] @2880
//   region KV @9216  [9216]: k-stage [128][36] @9216, v-stage @13824;
//                             then VMh/VMl bf16 [128][40] @9216; phase C: QFh/QFl [128][72]
//   s_q @18432 [9216]: q fp32 [256][36]
//   s_w @27648 [1056]
__global__ void __launch_bounds__(256, 2) attn_kernel(const int*   __restrict__ pm,
                                                      const float* __restrict__ qfw,
                                                      const float* __restrict__ qfb,
                                                      const float* __restrict__ kfw,
                                                      const float* __restrict__ kfb) {
    extern __shared__ float sm[];
    __nv_bfloat16* KFh = (__nv_bfloat16*)sm;        // [128][72]
    __nv_bfloat16* KFl = KFh + 9216;
    float* kstage = sm + 9216;                       // [128][36]
    float* vstage = sm + 13824;                      // [128][36]
    __nv_bfloat16* VMh = (__nv_bfloat16*)(sm + 9216);   // [128][40]
    __nv_bfloat16* VMl = VMh + 5120;
    float* s_q = sm + 18432;                         // [256][36]
    float* s_w = sm + 27648;                         // [1056]

    unsigned ksu = smem_u32p(kstage);
    unsigned vsu = smem_u32p(vstage);
    unsigned squ = smem_u32p(s_q);

    int tid = threadIdx.x;
    int r = blockIdx.x, h = blockIdx.y;
    int t0 = r * 256;
    int lane = tid & 31, w = tid >> 5;

    // ---- prologue: {k0,v0} group, {q} group ----
    {
        const float* Pk0 = g_P + (size_t)t0 * 512 + 128 + h * 32;
        const float* Pv0 = g_P + (size_t)t0 * 512 + 256 + h * 32;
        #pragma unroll
        for (int it = 0; it < 4; it++) {
            int idx = it * 256 + tid;
            int token = idx >> 3, c4 = idx & 7;
            cpasync16(ksu + (unsigned)(token * 36 + c4 * 4) * 4,
                      Pk0 + (size_t)token * 512 + c4 * 4);
            cpasync16(vsu + (unsigned)(token * 36 + c4 * 4) * 4,
                      Pv0 + (size_t)token * 512 + c4 * 4);
        }
        CP_COMMIT();
        const float* Pq0 = g_P + (size_t)t0 * 512 + h * 32;
        #pragma unroll
        for (int it = 0; it < 8; it++) {
            int idx = it * 256 + tid;
            int token = idx >> 3, c4 = idx & 7;
            cpasync16(squ + (unsigned)(token * 36 + c4 * 4) * 4,
                      Pq0 + (size_t)token * 512 + c4 * 4);
        }
        CP_COMMIT();
    }

    for (int i = tid; i < 1024; i += 256) s_w[i] = kfw[i];
    if (tid < 32) s_w[1024 + tid] = kfb[tid];

    // ---- step B MMA decomposition: warp -> (m-tile, n-group) ----
    int mt = w & 3, nh = w >> 2;
    int ntN = nh ? 2 : 3;
    int nt0 = nh ? 3 : 0;
    int krow_a = (lane & 7) + ((lane >> 4) & 1) * 8;
    int mcol   = mt * 16 + ((lane >> 3) & 1) * 8;
    int krow_b = (lane & 7) + ((lane >> 3) & 1) * 8;
    unsigned KFhu = smem_u32p(KFh), KFlu = smem_u32p(KFl);
    unsigned VMhu = smem_u32p(VMh), VMlu = smem_u32p(VMl);

    float accB[3][4];
    #pragma unroll
    for (int ni = 0; ni < 3; ni++)
        #pragma unroll
        for (int c = 0; c < 4; c++) accB[ni][c] = 0.0f;

    #pragma unroll 1
    for (int c = 0; c < 2; c++) {
        if (c == 0) { CP_WAIT(1); } else { CP_WAIT(0); }
        __syncthreads();
        // ---- features: kf -> KFh/KFl bf16 ----
        {
            int tk = tid & 127, hh = tid >> 7;
            float mk = (float)pm[t0 + c * 128 + tk];
            const ulonglong2* kp = (const ulonglong2*)(kstage + tk * 36);
            u64 k2[16];
            #pragma unroll
            for (int i = 0; i < 8; i++) {
                ulonglong2 kk = kp[i];
                k2[2 * i] = kk.x; k2[2 * i + 1] = kk.y;
            }
            #pragma unroll
            for (int rr = 0; rr < 16; rr++) {
                int row = hh * 16 + rr;
                const u64* wr = (const u64*)&s_w[row * 32];
                u64 a2 = 0ull, b2 = 0ull;
                #pragma unroll
                for (int dp = 0; dp < 8; dp++) {
                    ffma2(a2, wr[2 * dp],     k2[2 * dp]);
                    ffma2(b2, wr[2 * dp + 1], k2[2 * dp + 1]);
                }
                float2 fa = funpk(a2), fb = funpk(b2);
                float m = (fa.x + fa.y) + (fb.x + fb.y) + s_w[1024 + row];
                m = fminf(8.0f, fmaxf(-8.0f, m));
                float e  = __expf(m)  * mk;
                float ei = __expf(-m) * mk;
                __nv_bfloat16 eh, el;
                bf16split(e, eh, el);
                KFh[tk * 72 + row] = eh; KFl[tk * 72 + row] = el;
                bf16split(ei, eh, el);
                KFh[tk * 72 + row + 32] = eh; KFl[tk * 72 + row + 32] = el;
            }
        }
        // ---- convert v -> VMh/VMl bf16 [128][40] (+ ones col 32, zeros 33-39) ----
        {
            int token = tid >> 1, dh = (tid & 1) * 16;
            float vv[16];
            const float* vp = vstage + token * 36 + dh;
            #pragma unroll
            for (int j = 0; j < 16; j++) vv[j] = vp[j];
            __syncthreads();   // all v reads done before VM writes (regions overlap)
            #pragma unroll
            for (int j = 0; j < 16; j++) {
                __nv_bfloat16 hh2, ll2; bf16split(vv[j], hh2, ll2);
                VMh[token * 40 + dh + j] = hh2;
                VMl[token * 40 + dh + j] = ll2;
            }
            if (tid < 128) {
                VMh[tid * 40 + 32] = __float2bfloat16_rn(1.0f);
                VMl[tid * 40 + 32] = __float2bfloat16_rn(0.0f);
                #pragma unroll
                for (int j = 33; j < 40; j++) {
                    VMh[tid * 40 + j] = __float2bfloat16_rn(0.0f);
                    VMl[tid * 40 + j] = __float2bfloat16_rn(0.0f);
                }
            }
        }
        __syncthreads();
        // ---- step B MMA: KV[64][40] += KF^T @ VM  (trans ldmatrix, K=128 tokens) ----
        #pragma unroll
        for (int kt = 0; kt < 8; kt++) {
            unsigned ah[4], al[4];
            unsigned ao = (unsigned)((kt * 16 + krow_a) * 144 + mcol * 2);
            ldmx4t(ah, KFhu + ao);
            ldmx4t(al, KFlu + ao);
            #pragma unroll
            for (int ni = 0; ni < 3; ni++) {
                if (ni < ntN) {
                    unsigned bo = (unsigned)((kt * 16 + krow_b) * 80 + (nt0 + ni) * 16);
                    unsigned bh2[2], bl2[2];
                    ldmx2t(bh2, VMhu + bo);
                    ldmx2t(bl2, VMlu + bo);
                    mma16816(accB[ni], ah, bh2);
                    mma16816(accB[ni], ah, bl2);
                    mma16816(accB[ni], al, bh2);
                }
            }
        }
        __syncthreads();   // MMA reads of KF/VM done before region reuse
        if (c == 0) {
            const float* Pk1 = g_P + (size_t)(t0 + 128) * 512 + 128 + h * 32;
            const float* Pv1 = g_P + (size_t)(t0 + 128) * 512 + 256 + h * 32;
            #pragma unroll
            for (int it = 0; it < 4; it++) {
                int idx = it * 256 + tid;
                int token = idx >> 3, c4 = idx & 7;
                cpasync16(ksu + (unsigned)(token * 36 + c4 * 4) * 4,
                          Pk1 + (size_t)token * 512 + c4 * 4);
                cpasync16(vsu + (unsigned)(token * 36 + c4 * 4) * 4,
                          Pv1 + (size_t)token * 512 + c4 * 4);
            }
            CP_COMMIT();
        }
    }

    // ---- write fragments -> KVTh/KVTl [40][72] (in KF region), reload qf weights ----
    __nv_bfloat16* KVTh = (__nv_bfloat16*)sm;
    __nv_bfloat16* KVTl = KVTh + 2880;
    float* gbuf = sm + 2880;                         // [128][36]
    unsigned gbu = smem_u32p(gbuf);
    #pragma unroll
    for (int ni = 0; ni < 3; ni++) {
        if (ni < ntN) {
            #pragma unroll
            for (int c = 0; c < 4; c++) {
                int f = mt * 16 + (lane >> 2) + ((c >> 1) ? 8 : 0);
                int n = (nt0 + ni) * 8 + (lane & 3) * 2 + (c & 1);
                if (n <= 32) {
                    __nv_bfloat16 hh2, ll2; bf16split(accB[ni][c], hh2, ll2);
                    KVTh[n * 72 + f] = hh2;
                    KVTl[n * 72 + f] = ll2;
                }
            }
        }
    }
    // zero KVT rows 33..39
    for (int i = tid; i < 504; i += 256) {
        KVTh[2376 + i] = __float2bfloat16_rn(0.0f);
        KVTl[2376 + i] = __float2bfloat16_rn(0.0f);
    }
    for (int i = tid; i < 1024; i += 256) s_w[i] = qfw[i];
    if (tid < 32) s_w[1024 + tid] = qfb[tid];
    __syncthreads();

    // ---- issue g (pass 0) into gbuf ----
    {
        const float* Pg0 = g_P + (size_t)t0 * 512 + 384 + h * 32;
        #pragma unroll
        for (int it = 0; it < 4; it++) {
            int idx = it * 256 + tid;
            int token = idx >> 3, c4 = idx & 7;
            cpasync16(gbu + (unsigned)(token * 36 + c4 * 4) * 4,
                      Pg0 + (size_t)token * 512 + c4 * 4);
        }
        CP_COMMIT();
    }

    // ---- step C: two M=128 passes, QF bf16-split in KV region ----
    __nv_bfloat16* QFh = (__nv_bfloat16*)(sm + 9216);   // [128][72]
    __nv_bfloat16* QFl = QFh + 9216;
    unsigned QFhu = smem_u32p(QFh), QFlu = smem_u32p(QFl);
    unsigned KVThu = smem_u32p(KVTh), KVTlu = smem_u32p(KVTl);
    int warp_m = w * 16;
    int arow = warp_m + (lane & 15);
    int kofa = (lane >> 4) * 8;
    int brow8 = lane & 7;
    int kofb = ((lane >> 3) & 1) * 8;

    #pragma unroll 1
    for (int p = 0; p < 2; p++) {
        {
            int tk = tid & 127, hh = tid >> 7;
            const ulonglong2* qp = (const ulonglong2*)(s_q + (p * 128 + tk) * 36);
            u64 q2[16];
            #pragma unroll
            for (int i = 0; i < 8; i++) {
                ulonglong2 qq = qp[i];
                q2[2 * i] = qq.x; q2[2 * i + 1] = qq.y;
            }
            #pragma unroll
            for (int rr = 0; rr < 16; rr++) {
                int row = hh * 16 + rr;
                const u64* wr = (const u64*)&s_w[row * 32];
                u64 a2 = 0ull, b2 = 0ull;
                #pragma unroll
                for (int dp = 0; dp < 8; dp++) {
                    ffma2(a2, wr[2 * dp],     q2[2 * dp]);
                    ffma2(b2, wr[2 * dp + 1], q2[2 * dp + 1]);
                }
                float2 fa = funpk(a2), fb = funpk(b2);
                float m = (fa.x + fa.y) + (fb.x + fb.y) + s_w[1024 + row];
                m = fminf(8.0f, fmaxf(-8.0f, m));
                float e  = __expf(m);
                float ei = __expf(-m);
                __nv_bfloat16 eh, el; bf16split(e, eh, el);
                QFh[tk * 72 + row] = eh; QFl[tk * 72 + row] = el;
                bf16split(ei, eh, el);
                QFh[tk * 72 + row + 32] = eh; QFl[tk * 72 + row + 32] = el;
            }
        }
        __syncthreads();

        float acc[5][4];
        #pragma unroll
        for (int ni = 0; ni < 5; ni++)
            #pragma unroll
            for (int c2 = 0; c2 < 4; c2++) acc[ni][c2] = 0.0f;
        #pragma unroll
        for (int ks2 = 0; ks2 < 4; ks2++) {
            unsigned ah[4], al[4];
            unsigned ao = (unsigned)(arow * 144 + (ks2 * 16 + kofa) * 2);
            ldmx4(ah, QFhu + ao);
            ldmx4(al, QFlu + ao);
            #pragma unroll
            for (int ni = 0; ni < 5; ni++) {
                unsigned bo = (unsigned)((ni * 8 + brow8) * 144 + (ks2 * 16 + kofb) * 2);
                unsigned bh2[2], bl2[2];
                ldmx2(bh2, KVThu + bo);
                ldmx2(bl2, KVTlu + bo);
                mma16816(acc[ni], ah, bh2);
                mma16816(acc[ni], ah, bl2);
                mma16816(acc[ni], al, bh2);
            }
        }
        CP_WAIT(0);
        __syncthreads();

        {
            int srcl = lane & ~3;
            float den0 = __shfl_sync(0xFFFFFFFFu, acc[4][0], srcl);
            float den1 = __shfl_sync(0xFFFFFFFFu, acc[4][2], srcl);
            float inv0 = 1.0f / fmaxf(den0, 1e-6f);
            float inv1 = 1.0f / fmaxf(den1, 1e-6f);
            int row0 = warp_m + (lane >> 2);
            int row1 = row0 + 8;
            float* GAbase = g_GA + (size_t)(t0 + p * 128) * 128 + h * 32;
            #pragma unroll
            for (int ni = 0; ni < 4; ni++) {
                int col = ni * 8 + (lane & 3) * 2;
                float2 g0 = *(const float2*)&gbuf[row0 * 36 + col];
                float2 g1 = *(const float2*)&gbuf[row1 * 36 + col];
                float2 o0, o1;
                o0.x = __fdividef(1.0f, 1.0f + __expf(-g0.x)) * acc[ni][0] * inv0;
                o0.y = __fdividef(1.0f, 1.0f + __expf(-g0.y)) * acc[ni][1] * inv0;
                o1.x = __fdividef(1.0f, 1.0f + __expf(-g1.x)) * acc[ni][2] * inv1;
                o1.y = __fdividef(1.0f, 1.0f + __expf(-g1.y)) * acc[ni][3] * inv1;
                *(float2*)(GAbase + (size_t)row0 * 128 + col) = o0;
                *(float2*)(GAbase + (size_t)row1 * 128 + col) = o1;
            }
        }
        __syncthreads();
        if (p == 0) {
            const float* Pg1 = g_P + (size_t)(t0 + 128) * 512 + 384 + h * 32;
            #pragma unroll
            for (int it = 0; it < 4; it++) {
                int idx = it * 256 + tid;
                int token = idx >> 3, c4 = idx & 7;
                cpasync16(gbu + (unsigned)(token * 36 + c4 * 4) * 4,
                          Pg1 + (size_t)token * 512 + c4 * 4);
            }
            CP_COMMIT();
        }
    }
}

// ---------------- launcher ----------------
extern "C" void kernel_launch(void* const* d_in, const int* in_sizes, int n_in,
                              void* d_out, int out_size) {
    const float* z    = (const float*)d_in[0];
    const int*   pm   = (const int*)  d_in[1];
    const float* lnw  = (const float*)d_in[2];
    const float* lnb  = (const float*)d_in[3];
    const float* qw   = (const float*)d_in[4];
    const float* qb   = (const float*)d_in[5];
    const float* kw   = (const float*)d_in[6];
    const float* kb   = (const float*)d_in[7];
    const float* vw   = (const float*)d_in[8];
    const float* vb   = (const float*)d_in[9];
    const float* qfw  = (const float*)d_in[10];
    const float* qfb  = (const float*)d_in[11];
    const float* kfw  = (const float*)d_in[12];
    const float* kfb  = (const float*)d_in[13];
    const float* gw   = (const float*)d_in[14];
    const float* gb   = (const float*)d_in[15];
    const float* ow   = (const float*)d_in[16];
    const float* ob   = (const float*)d_in[17];
    float* out = (float*)d_out;

    static int attr_set = 0;
    if (!attr_set) {
        cudaFuncSetAttribute(attn_kernel, cudaFuncAttributeMaxDynamicSharedMemorySize, 114816);
        cudaFuncSetAttribute(gemm_proj,   cudaFuncAttributeMaxDynamicSharedMemorySize, 61440);
        cudaFuncSetAttribute(mma_gemm2,   cudaFuncAttributeMaxDynamicSharedMemorySize, 104448);
        attr_set = 1;
    }

    pack_kernel<<<320, 256>>>(qw, kw, vw, gw, qb, kb, vb, gb, ow);
    ln_kernel<<<8192, 256>>>(z, lnw, lnb);
    gemm_proj<<<dim3(1024, 4), 256, 61440>>>();
    attn_kernel<<<dim3(256, 4), 256, 114816>>>(pm, qfw, qfb, kfw, kfb);
    mma_gemm2<<<dim3(1024, 1), 256, 104448>>>(ob, pm, out);
}